// round 2
// baseline (speedup 1.0000x reference)
#include <cuda_runtime.h>
#include <math.h>

#define NN 10000
#define EE 160000
#define GG 64
#define HH 4
#define EDIM 32

// ---------------- static scratch ----------------
__device__ int   g_deg[NN];
__device__ int   g_rowptr[NN + 1];
__device__ int   g_cursor[NN];
__device__ int   g_eperm[EE];
__device__ float g_y[(size_t)NN * 1024];      // aggregated x-space features [N, H*K]
__device__ float g_hA[(size_t)NN * 256];
__device__ float g_hB[(size_t)NN * 256];
__device__ float g_alsrc[NN * HH];
__device__ float g_aldst[NN * HH];
__device__ float g_ale[(size_t)EE * HH];
__device__ float g_expw[(size_t)EE * HH];     // fallback only
__device__ float g_M[EDIM * HH];
__device__ float g_Was[HH * 256];
__device__ float g_Wad[HH * 256];
__device__ float g_wstack[262144];            // [H*K, C] stacked, pre-scaled by 1/H
__device__ int   g_gcnt[GG];

// ---------------- CSR build ----------------
__global__ void k_deg(const int* __restrict__ dst) {
    int e = blockIdx.x * blockDim.x + threadIdx.x;
    if (e < EE) atomicAdd(&g_deg[dst[e]], 1);
}

__global__ void k_scan() {
    __shared__ int sh[1024];
    __shared__ int carry;
    int tid = threadIdx.x;
    if (tid == 0) { carry = 0; g_rowptr[0] = 0; }
    __syncthreads();
    for (int base = 0; base < NN; base += 1024) {
        int i = base + tid;
        int v = (i < NN) ? g_deg[i] : 0;
        sh[tid] = v;
        __syncthreads();
        for (int off = 1; off < 1024; off <<= 1) {
            int t = (tid >= off) ? sh[tid - off] : 0;
            __syncthreads();
            sh[tid] += t;
            __syncthreads();
        }
        int inc = sh[tid];
        int cl = carry;
        if (i < NN) {
            g_rowptr[i + 1] = cl + inc;
            g_cursor[i] = cl + inc - v;
        }
        __syncthreads();
        if (tid == 0) carry = cl + sh[1023];
        __syncthreads();
    }
}

__global__ void k_scatter(const int* __restrict__ dst) {
    int e = blockIdx.x * blockDim.x + threadIdx.x;
    if (e < EE) {
        int p = atomicAdd(&g_cursor[dst[e]], 1);
        g_eperm[p] = e;
    }
}

// ---------------- weight preprocessing ----------------
// Wa_s[h*K+k] = sum_c W[k, h*C+c] * a_s[h,c]   (same for a_d)
__global__ void k_wa(const float* __restrict__ W, const float* __restrict__ a_s,
                     const float* __restrict__ a_d, int KD, int C) {
    int i = blockIdx.x * blockDim.x + threadIdx.x;
    if (i >= KD * HH) return;
    int k = i / HH, h = i % HH;
    float s = 0.f, d = 0.f;
    const float* wrow = W + (size_t)k * HH * C + h * C;
    const float* as = a_s + h * C;
    const float* ad = a_d + h * C;
    for (int c = 0; c < C; c++) { float w = wrow[c]; s += w * as[c]; d += w * ad[c]; }
    g_Was[h * KD + k] = s;
    g_Wad[h * KD + k] = d;
}

// M[d,h] = sum_c We[d, h*C+c] * a_e[h,c]
__global__ void k_M(const float* __restrict__ We, const float* __restrict__ ae, int C) {
    int i = threadIdx.x;
    if (i >= EDIM * HH) return;
    int d = i / HH, h = i % HH;
    float s = 0.f;
    for (int c = 0; c < C; c++) s += We[(size_t)d * HH * C + h * C + c] * ae[h * C + c];
    g_M[d * HH + h] = s;
}

// Wstack[(h*K+k)*C + c] = W[k, h*C + c] / H
__global__ void k_wstack(const float* __restrict__ W, int KD, int C) {
    int total = HH * KD * C;
    for (int idx = blockIdx.x * blockDim.x + threadIdx.x; idx < total;
         idx += gridDim.x * blockDim.x) {
        int h = idx / (KD * C);
        int rem = idx % (KD * C);
        int k = rem / C;
        int c = rem % C;
        g_wstack[idx] = W[(size_t)k * HH * C + h * C + c] * 0.25f;
    }
}

// ---------------- per-edge attention logits ----------------
__global__ void k_ale(const float* __restrict__ eattr) {
    __shared__ float Ms[EDIM * HH];
    if (threadIdx.x < EDIM * HH) Ms[threadIdx.x] = g_M[threadIdx.x];
    __syncthreads();
    int e = blockIdx.x * blockDim.x + threadIdx.x;
    if (e >= EE) return;
    float a[HH] = {0.f, 0.f, 0.f, 0.f};
    const float4* ep = (const float4*)(eattr + (size_t)e * EDIM);
#pragma unroll
    for (int q = 0; q < EDIM / 4; q++) {
        float4 v = ep[q];
        int d = q * 4;
#pragma unroll
        for (int h = 0; h < HH; h++) {
            a[h] += v.x * Ms[(d + 0) * HH + h] + v.y * Ms[(d + 1) * HH + h]
                  + v.z * Ms[(d + 2) * HH + h] + v.w * Ms[(d + 3) * HH + h];
        }
    }
    *(float4*)(g_ale + (size_t)e * HH) = make_float4(a[0], a[1], a[2], a[3]);
}

// ---------------- per-node attention coefficients: al = x @ Wa ----------------
__global__ void k_al(const float* __restrict__ x, int KD) {
    __shared__ float Was[HH * 256];
    __shared__ float Wad[HH * 256];
    int tid = threadIdx.x;                 // 256 threads = 8 warps
    for (int i = tid; i < HH * KD; i += 256) { Was[i] = g_Was[i]; Wad[i] = g_Wad[i]; }
    __syncthreads();
    int lane = tid & 31;
    int n = blockIdx.x * 8 + (tid >> 5);
    if (n >= NN) return;
    float s[HH] = {0, 0, 0, 0}, d[HH] = {0, 0, 0, 0};
    const float* xrow = x + (size_t)n * KD;
    for (int k = lane; k < KD; k += 32) {
        float xv = xrow[k];
#pragma unroll
        for (int h = 0; h < HH; h++) {
            s[h] += xv * Was[h * KD + k];
            d[h] += xv * Wad[h * KD + k];
        }
    }
#pragma unroll
    for (int h = 0; h < HH; h++)
#pragma unroll
        for (int o = 16; o; o >>= 1) {
            s[h] += __shfl_xor_sync(0xffffffffu, s[h], o);
            d[h] += __shfl_xor_sync(0xffffffffu, d[h], o);
        }
    if (lane == 0) {
        *(float4*)(g_alsrc + n * HH) = make_float4(s[0], s[1], s[2], s[3]);
        *(float4*)(g_aldst + n * HH) = make_float4(d[0], d[1], d[2], d[3]);
    }
}

// ---------------- fused segment-softmax + x-space aggregation ----------------
__device__ __forceinline__ float lrelu(float v) { return v >= 0.f ? v : 0.2f * v; }

template <int KD>
__global__ void __launch_bounds__(128) k_fsa(const int* __restrict__ src,
                                             const float* __restrict__ x,
                                             float* __restrict__ y) {
    constexpr int CAP = 512;
    constexpr int R = KD / 128;
    __shared__ int   ss[CAP];
    __shared__ float sw[HH][CAP];
    __shared__ float red[32];
    __shared__ float bc[12];     // [0..3]=mx, [4..7]=loopw, [8..11]=invs

    int n = blockIdx.x;
    int tid = threadIdx.x, lane = tid & 31, wrp = tid >> 5;
    int st = g_rowptr[n], en = g_rowptr[n + 1];
    int deg = en - st;
    bool cached = (deg <= CAP);

    float4 ad4 = *(const float4*)(g_aldst + n * HH);
    float4 an4 = *(const float4*)(g_alsrc + n * HH);
    float adst[HH] = {ad4.x, ad4.y, ad4.z, ad4.w};
    float asrcn[HH] = {an4.x, an4.y, an4.z, an4.w};

    // phase A: logits, running max, sum of ale
    float lmx[HH] = {-1e30f, -1e30f, -1e30f, -1e30f};
    float lsa[HH] = {0, 0, 0, 0};
    for (int j = tid; j < deg; j += 128) {
        int e = g_eperm[st + j];
        int s = src[e];
        float4 al4 = *(const float4*)(g_ale + (size_t)e * HH);
        float4 as4 = *(const float4*)(g_alsrc + (size_t)s * HH);
        float l0 = lrelu(as4.x + adst[0] + al4.x);
        float l1 = lrelu(as4.y + adst[1] + al4.y);
        float l2 = lrelu(as4.z + adst[2] + al4.z);
        float l3 = lrelu(as4.w + adst[3] + al4.w);
        lsa[0] += al4.x; lsa[1] += al4.y; lsa[2] += al4.z; lsa[3] += al4.w;
        lmx[0] = fmaxf(lmx[0], l0); lmx[1] = fmaxf(lmx[1], l1);
        lmx[2] = fmaxf(lmx[2], l2); lmx[3] = fmaxf(lmx[3], l3);
        if (cached) {
            ss[j] = s;
            sw[0][j] = l0; sw[1][j] = l1; sw[2][j] = l2; sw[3][j] = l3;
        }
    }
#pragma unroll
    for (int h = 0; h < HH; h++)
#pragma unroll
        for (int o = 16; o; o >>= 1) {
            lmx[h] = fmaxf(lmx[h], __shfl_xor_sync(0xffffffffu, lmx[h], o));
            lsa[h] += __shfl_xor_sync(0xffffffffu, lsa[h], o);
        }
    if (lane == 0) {
#pragma unroll
        for (int h = 0; h < HH; h++) { red[wrp * 8 + h] = lmx[h]; red[wrp * 8 + 4 + h] = lsa[h]; }
    }
    __syncthreads();
    if (tid == 0) {
        float inv = 1.f / (float)(deg > 0 ? deg : 1);
#pragma unroll
        for (int h = 0; h < HH; h++) {
            float m = fmaxf(fmaxf(red[h], red[8 + h]), fmaxf(red[16 + h], red[24 + h]));
            float sa = red[4 + h] + red[12 + h] + red[20 + h] + red[28 + h];
            float llog = lrelu(asrcn[h] + adst[h] + sa * inv);
            m = fmaxf(m, llog);
            bc[h] = m;
            bc[4 + h] = expf(llog - m);     // self-loop exp weight
        }
    }
    __syncthreads();
    float mx[HH] = {bc[0], bc[1], bc[2], bc[3]};

    // phase exp
    float lse[HH] = {0, 0, 0, 0};
    for (int j = tid; j < deg; j += 128) {
        float l[HH];
        int e = -1;
        if (cached) {
#pragma unroll
            for (int h = 0; h < HH; h++) l[h] = sw[h][j];
        } else {
            e = g_eperm[st + j];
            int s = src[e];
            float4 al4 = *(const float4*)(g_ale + (size_t)e * HH);
            float4 as4 = *(const float4*)(g_alsrc + (size_t)s * HH);
            l[0] = lrelu(as4.x + adst[0] + al4.x);
            l[1] = lrelu(as4.y + adst[1] + al4.y);
            l[2] = lrelu(as4.z + adst[2] + al4.z);
            l[3] = lrelu(as4.w + adst[3] + al4.w);
        }
        float w[HH];
#pragma unroll
        for (int h = 0; h < HH; h++) { w[h] = expf(l[h] - mx[h]); lse[h] += w[h]; }
        if (cached) {
#pragma unroll
            for (int h = 0; h < HH; h++) sw[h][j] = w[h];
        } else {
            *(float4*)(g_expw + (size_t)e * HH) = make_float4(w[0], w[1], w[2], w[3]);
        }
    }
#pragma unroll
    for (int h = 0; h < HH; h++)
#pragma unroll
        for (int o = 16; o; o >>= 1) lse[h] += __shfl_xor_sync(0xffffffffu, lse[h], o);
    if (lane == 0) {
#pragma unroll
        for (int h = 0; h < HH; h++) red[wrp * 8 + h] = lse[h];
    }
    __syncthreads();
    if (tid == 0) {
#pragma unroll
        for (int h = 0; h < HH; h++) {
            float s = red[h] + red[8 + h] + red[16 + h] + red[24 + h];
            bc[8 + h] = 1.f / (s + bc[4 + h] + 1e-16f);
        }
    }
    __syncthreads();

    // phase B: aggregate x[src] with weights (threads = channels)
    float acc[R][HH];
#pragma unroll
    for (int r = 0; r < R; r++)
#pragma unroll
        for (int h = 0; h < HH; h++) acc[r][h] = 0.f;

    for (int j = 0; j < deg; j++) {
        int s;
        float w0, w1, w2, w3;
        if (cached) {
            s = ss[j];
            w0 = sw[0][j]; w1 = sw[1][j]; w2 = sw[2][j]; w3 = sw[3][j];
        } else {
            int e = g_eperm[st + j];
            s = src[e];
            float4 w4 = *(const float4*)(g_expw + (size_t)e * HH);
            w0 = w4.x; w1 = w4.y; w2 = w4.z; w3 = w4.w;
        }
        const float* xrow = x + (size_t)s * KD;
#pragma unroll
        for (int r = 0; r < R; r++) {
            float xv = xrow[tid + r * 128];
            acc[r][0] += w0 * xv; acc[r][1] += w1 * xv;
            acc[r][2] += w2 * xv; acc[r][3] += w3 * xv;
        }
    }
    // self loop
    {
        const float* xrow = x + (size_t)n * KD;
#pragma unroll
        for (int r = 0; r < R; r++) {
            float xv = xrow[tid + r * 128];
            acc[r][0] += bc[4] * xv; acc[r][1] += bc[5] * xv;
            acc[r][2] += bc[6] * xv; acc[r][3] += bc[7] * xv;
        }
    }
    float* yrow = y + (size_t)n * (HH * KD);
#pragma unroll
    for (int r = 0; r < R; r++)
#pragma unroll
        for (int h = 0; h < HH; h++)
            yrow[h * KD + r * 128 + tid] = acc[r][h] * bc[8 + h];
}

// ---------------- GEMM: C[M,Ncol] = A[M,K]@B[K,Ncol] + bias, ELU, double-buffered ----------------
#define BM 64
#define BN 64
#define BK 16
__global__ void __launch_bounds__(256) k_gemm(const float* __restrict__ A,
                                              const float* __restrict__ B,
                                              const float* __restrict__ bias,
                                              float* __restrict__ C,
                                              int M, int K, int Ncol) {
    __shared__ float As[2][BK][BM];
    __shared__ float Bs[2][BK][BN];
    int tid = threadIdx.x;
    int tx = tid & 15, ty = tid >> 4;
    int row0 = blockIdx.y * BM, col0 = blockIdx.x * BN;

    int ar = tid >> 2;                // 0..63
    int ak = (tid & 3) * 4;           // 0,4,8,12
    int bk = tid >> 4;                // 0..15
    int bc = (tid & 15) * 4;          // 0..60
    int arow = row0 + ar;
    bool arok = (arow < M);

    float acc[4][4];
#pragma unroll
    for (int i = 0; i < 4; i++)
#pragma unroll
        for (int j = 0; j < 4; j++) acc[i][j] = 0.f;

    int nsteps = K / BK;
    // prologue: load step 0
    float4 av = arok ? *(const float4*)(A + (size_t)arow * K + ak)
                     : make_float4(0, 0, 0, 0);
    float4 bv = *(const float4*)(B + (size_t)bk * Ncol + col0 + bc);
    As[0][ak + 0][ar] = av.x; As[0][ak + 1][ar] = av.y;
    As[0][ak + 2][ar] = av.z; As[0][ak + 3][ar] = av.w;
    *(float4*)&Bs[0][bk][bc] = bv;
    __syncthreads();

    for (int s = 0; s < nsteps; s++) {
        int cur = s & 1, nxt = cur ^ 1;
        if (s + 1 < nsteps) {
            int k0 = (s + 1) * BK;
            av = arok ? *(const float4*)(A + (size_t)arow * K + k0 + ak)
                      : make_float4(0, 0, 0, 0);
            bv = *(const float4*)(B + (size_t)(k0 + bk) * Ncol + col0 + bc);
        }
#pragma unroll
        for (int kk = 0; kk < BK; kk++) {
            float4 a4 = *(const float4*)&As[cur][kk][ty * 4];
            float4 b4 = *(const float4*)&Bs[cur][kk][tx * 4];
            float a[4] = {a4.x, a4.y, a4.z, a4.w};
            float b[4] = {b4.x, b4.y, b4.z, b4.w};
#pragma unroll
            for (int i = 0; i < 4; i++)
#pragma unroll
                for (int j = 0; j < 4; j++) acc[i][j] += a[i] * b[j];
        }
        if (s + 1 < nsteps) {
            As[nxt][ak + 0][ar] = av.x; As[nxt][ak + 1][ar] = av.y;
            As[nxt][ak + 2][ar] = av.z; As[nxt][ak + 3][ar] = av.w;
            *(float4*)&Bs[nxt][bk][bc] = bv;
            __syncthreads();
        }
    }

#pragma unroll
    for (int i = 0; i < 4; i++) {
        int r = row0 + ty * 4 + i;
        if (r < M) {
#pragma unroll
            for (int j = 0; j < 4; j++) {
                int c = col0 + tx * 4 + j;
                float v = acc[i][j] + bias[c];
                v = v > 0.f ? v : expm1f(v);
                C[(size_t)r * Ncol + c] = v;
            }
        }
    }
}

// ---------------- graph mean pooling ----------------
__global__ void k_gcnt(const int* __restrict__ batch) {
    int n = blockIdx.x * blockDim.x + threadIdx.x;
    if (n < NN) atomicAdd(&g_gcnt[batch[n]], 1);
}

__global__ void k_pool(const int* __restrict__ batch, const float* __restrict__ h,
                       float* __restrict__ out) {
    int n = blockIdx.x;
    int t = threadIdx.x;  // 128
    atomicAdd(&out[(size_t)batch[n] * 128 + t], h[(size_t)n * 128 + t]);
}

__global__ void k_pooldiv(float* __restrict__ out) {
    int i = blockIdx.x * blockDim.x + threadIdx.x;
    if (i < GG * 128) {
        int g = i / 128;
        int c = g_gcnt[g];
        out[i] /= (float)(c > 0 ? c : 1);
    }
}

// ---------------- launch ----------------
extern "C" void kernel_launch(void* const* d_in, const int* in_sizes, int n_in,
                              void* d_out, int out_size) {
    const float* x     = (const float*)d_in[0];
    const int*   ei    = (const int*)d_in[1];
    const float* eattr = (const float*)d_in[2];
    const int*   batch = (const int*)d_in[3];
    const int* src = ei;
    const int* dst = ei + EE;

    const float* W[3]  = {(const float*)d_in[4],  (const float*)d_in[10], (const float*)d_in[16]};
    const float* We[3] = {(const float*)d_in[5],  (const float*)d_in[11], (const float*)d_in[17]};
    const float* As[3] = {(const float*)d_in[6],  (const float*)d_in[12], (const float*)d_in[18]};
    const float* Ad[3] = {(const float*)d_in[7],  (const float*)d_in[13], (const float*)d_in[19]};
    const float* Ae[3] = {(const float*)d_in[8],  (const float*)d_in[14], (const float*)d_in[20]};
    const float* Bb[3] = {(const float*)d_in[9],  (const float*)d_in[15], (const float*)d_in[21]};
    (void)n_in; (void)in_sizes; (void)out_size;

    float* out = (float*)d_out;

    void *p_deg, *p_gcnt, *p_y, *p_hA, *p_hB, *p_ws;
    cudaGetSymbolAddress(&p_deg, g_deg);
    cudaGetSymbolAddress(&p_gcnt, g_gcnt);
    cudaGetSymbolAddress(&p_y, g_y);
    cudaGetSymbolAddress(&p_hA, g_hA);
    cudaGetSymbolAddress(&p_hB, g_hB);
    cudaGetSymbolAddress(&p_ws, g_wstack);
    float* y  = (float*)p_y;
    float* hA = (float*)p_hA;
    float* hB = (float*)p_hB;
    float* ws = (float*)p_ws;

    cudaMemsetAsync(p_deg, 0, NN * sizeof(int));
    cudaMemsetAsync(p_gcnt, 0, GG * sizeof(int));
    cudaMemsetAsync(out, 0, (size_t)GG * 128 * sizeof(float));

    // CSR build
    k_deg<<<(EE + 255) / 256, 256>>>(dst);
    k_scan<<<1, 1024>>>();
    k_scatter<<<(EE + 255) / 256, 256>>>(dst);

    const int Kdim[3] = {128, 128, 256};   // input dim per layer
    const int Cdim[3] = {128, 256, 128};   // output dim per layer
    const float* lin[3]  = {x, hA, hB};
    float*       lout[3] = {hA, hB, hA};

    for (int l = 0; l < 3; l++) {
        int Kd = Kdim[l], Cd = Cdim[l];
        // weight preprocessing
        k_wa<<<(Kd * HH + 127) / 128, 128>>>(W[l], As[l], Ad[l], Kd, Cd);
        k_M<<<1, 128>>>(We[l], Ae[l], Cd);
        k_wstack<<<256, 256>>>(W[l], Kd, Cd);
        // attention inputs
        k_ale<<<(EE + 127) / 128, 128>>>(eattr);
        k_al<<<(NN + 7) / 8, 256>>>(lin[l], Kd);
        // fused softmax + aggregation into y [N, H*Kd]
        if (Kd == 128)
            k_fsa<128><<<NN, 128>>>(src, lin[l], y);
        else
            k_fsa<256><<<NN, 128>>>(src, lin[l], y);
        // out = y @ Wstack + b, ELU
        int Kg = HH * Kd;
        dim3 gg(Cd / BN, (NN + BM - 1) / BM);
        k_gemm<<<gg, 256>>>(y, ws, Bb[l], lout[l], NN, Kg, Cd);
    }

    k_gcnt<<<(NN + 255) / 256, 256>>>(batch);
    k_pool<<<NN, 128>>>(batch, hA, out);
    k_pooldiv<<<(GG * 128 + 255) / 256, 256>>>(out);
}

// round 3
// speedup vs baseline: 1.1356x; 1.1356x over previous
#include <cuda_runtime.h>
#include <math.h>

#define NN 10000
#define EE 160000
#define GG 64
#define HH 4
#define EDIM 32

// ---------------- static scratch ----------------
__device__ int   g_deg[NN];
__device__ int   g_rowptr[NN + 1];
__device__ int   g_cursor[NN];
__device__ int   g_eperm[EE];
__device__ float g_y[(size_t)NN * 1024];      // aggregated x-space features [N, H*K]
__device__ float g_hA[(size_t)NN * 256];
__device__ float g_hB[(size_t)NN * 256];
__device__ float g_alsrc[NN * HH];
__device__ float g_aldst[NN * HH];
__device__ float g_ale[(size_t)EE * HH];
__device__ float g_expw[(size_t)EE * HH];     // fallback only (deg > 512)
__device__ float g_M[EDIM * HH];
__device__ float g_Was[HH * 256];
__device__ float g_Wad[HH * 256];
__device__ float g_wstack[262144];            // [H*K, C] stacked, pre-scaled by 1/H
__device__ int   g_gcnt[GG];

// ---------------- CSR build ----------------
__global__ void k_deg(const int* __restrict__ dst) {
    int e = blockIdx.x * blockDim.x + threadIdx.x;
    if (e < EE) atomicAdd(&g_deg[dst[e]], 1);
}

__global__ void k_scan() {
    __shared__ int sh[1024];
    __shared__ int carry;
    int tid = threadIdx.x;
    if (tid == 0) { carry = 0; g_rowptr[0] = 0; }
    __syncthreads();
    for (int base = 0; base < NN; base += 1024) {
        int i = base + tid;
        int v = (i < NN) ? g_deg[i] : 0;
        sh[tid] = v;
        __syncthreads();
        for (int off = 1; off < 1024; off <<= 1) {
            int t = (tid >= off) ? sh[tid - off] : 0;
            __syncthreads();
            sh[tid] += t;
            __syncthreads();
        }
        int inc = sh[tid];
        int cl = carry;
        if (i < NN) {
            g_rowptr[i + 1] = cl + inc;
            g_cursor[i] = cl + inc - v;
        }
        __syncthreads();
        if (tid == 0) carry = cl + sh[1023];
        __syncthreads();
    }
}

__global__ void k_scatter(const int* __restrict__ dst) {
    int e = blockIdx.x * blockDim.x + threadIdx.x;
    if (e < EE) {
        int p = atomicAdd(&g_cursor[dst[e]], 1);
        g_eperm[p] = e;
    }
}

// ---------------- fused weight preprocessing ----------------
// Region A (wa_blocks): Wa_s[h*K+k] = sum_c W[k,h*C+c]*a_s[h,c]; same for a_d.
//   warp per (k,h), lanes over c (coalesced).
// Region B (16 blocks): M[d,h] = sum_c We[d,h*C+c]*a_e[h,c]; warp per (d,h).
// Region C (64 blocks): Wstack[(h*K+k)*C+c] = W[k,h*C+c] * 0.25 (grid-stride copy).
__global__ void __launch_bounds__(256) k_prep(const float* __restrict__ W,
                                              const float* __restrict__ We,
                                              const float* __restrict__ a_s,
                                              const float* __restrict__ a_d,
                                              const float* __restrict__ a_e,
                                              int KD, int C, int wa_blocks) {
    int b = blockIdx.x;
    int lane = threadIdx.x & 31;
    int wrp = threadIdx.x >> 5;
    if (b < wa_blocks) {
        int idx = b * 8 + wrp;              // (k,h) index
        if (idx < KD * HH) {
            int k = idx / HH, h = idx % HH;
            const float* wrow = W + (size_t)k * HH * C + h * C;
            const float* as = a_s + h * C;
            const float* ad = a_d + h * C;
            float s = 0.f, d = 0.f;
            for (int c = lane; c < C; c += 32) {
                float w = wrow[c];
                s += w * as[c];
                d += w * ad[c];
            }
#pragma unroll
            for (int o = 16; o; o >>= 1) {
                s += __shfl_xor_sync(0xffffffffu, s, o);
                d += __shfl_xor_sync(0xffffffffu, d, o);
            }
            if (lane == 0) { g_Was[h * KD + k] = s; g_Wad[h * KD + k] = d; }
        }
    } else if (b < wa_blocks + 16) {
        int idx = (b - wa_blocks) * 8 + wrp;  // (d,h)
        if (idx < EDIM * HH) {
            int d = idx / HH, h = idx % HH;
            const float* werow = We + (size_t)d * HH * C + h * C;
            const float* ae = a_e + h * C;
            float s = 0.f;
            for (int c = lane; c < C; c += 32) s += werow[c] * ae[c];
#pragma unroll
            for (int o = 16; o; o >>= 1) s += __shfl_xor_sync(0xffffffffu, s, o);
            if (lane == 0) g_M[d * HH + h] = s;
        }
    } else {
        int nb = gridDim.x - wa_blocks - 16;
        int t0 = (b - wa_blocks - 16) * 256 + threadIdx.x;
        int total = HH * KD * C;
        for (int idx = t0; idx < total; idx += nb * 256) {
            int h = idx / (KD * C);
            int rem = idx % (KD * C);
            int k = rem / C;
            int c = rem % C;
            g_wstack[idx] = W[(size_t)k * HH * C + h * C + c] * 0.25f;
        }
    }
}

// ---------------- per-edge attention logits ----------------
__global__ void k_ale(const float* __restrict__ eattr) {
    __shared__ float Ms[EDIM * HH];
    if (threadIdx.x < EDIM * HH) Ms[threadIdx.x] = g_M[threadIdx.x];
    __syncthreads();
    int e = blockIdx.x * blockDim.x + threadIdx.x;
    if (e >= EE) return;
    float a[HH] = {0.f, 0.f, 0.f, 0.f};
    const float4* ep = (const float4*)(eattr + (size_t)e * EDIM);
#pragma unroll
    for (int q = 0; q < EDIM / 4; q++) {
        float4 v = ep[q];
        int d = q * 4;
#pragma unroll
        for (int h = 0; h < HH; h++) {
            a[h] += v.x * Ms[(d + 0) * HH + h] + v.y * Ms[(d + 1) * HH + h]
                  + v.z * Ms[(d + 2) * HH + h] + v.w * Ms[(d + 3) * HH + h];
        }
    }
    *(float4*)(g_ale + (size_t)e * HH) = make_float4(a[0], a[1], a[2], a[3]);
}

// ---------------- per-node attention coefficients: al = x @ Wa ----------------
__global__ void k_al(const float* __restrict__ x, int KD) {
    __shared__ float Was[HH * 256];
    __shared__ float Wad[HH * 256];
    int tid = threadIdx.x;                 // 256 threads = 8 warps
    for (int i = tid; i < HH * KD; i += 256) { Was[i] = g_Was[i]; Wad[i] = g_Wad[i]; }
    __syncthreads();
    int lane = tid & 31;
    int n = blockIdx.x * 8 + (tid >> 5);
    if (n >= NN) return;
    float s[HH] = {0, 0, 0, 0}, d[HH] = {0, 0, 0, 0};
    const float* xrow = x + (size_t)n * KD;
    for (int k = lane; k < KD; k += 32) {
        float xv = xrow[k];
#pragma unroll
        for (int h = 0; h < HH; h++) {
            s[h] += xv * Was[h * KD + k];
            d[h] += xv * Wad[h * KD + k];
        }
    }
#pragma unroll
    for (int h = 0; h < HH; h++)
#pragma unroll
        for (int o = 16; o; o >>= 1) {
            s[h] += __shfl_xor_sync(0xffffffffu, s[h], o);
            d[h] += __shfl_xor_sync(0xffffffffu, d[h], o);
        }
    if (lane == 0) {
        *(float4*)(g_alsrc + n * HH) = make_float4(s[0], s[1], s[2], s[3]);
        *(float4*)(g_aldst + n * HH) = make_float4(d[0], d[1], d[2], d[3]);
    }
}

// ---------------- fused segment-softmax + x-space aggregation ----------------
__device__ __forceinline__ float lrelu(float v) { return v >= 0.f ? v : 0.2f * v; }

template <int KD>
__global__ void __launch_bounds__(128) k_fsa(const int* __restrict__ src,
                                             const float* __restrict__ x,
                                             float* __restrict__ y) {
    constexpr int CAP = 512;
    constexpr int R = KD / 128;
    __shared__ int   ss[CAP];
    __shared__ float sw[HH][CAP];
    __shared__ float red[32];
    __shared__ float bc[12];     // [0..3]=mx, [4..7]=loopw, [8..11]=invs

    int n = blockIdx.x;
    int tid = threadIdx.x, lane = tid & 31, wrp = tid >> 5;
    int st = g_rowptr[n], en = g_rowptr[n + 1];
    int deg = en - st;
    bool cached = (deg <= CAP);

    float4 ad4 = *(const float4*)(g_aldst + n * HH);
    float4 an4 = *(const float4*)(g_alsrc + n * HH);
    float adst[HH] = {ad4.x, ad4.y, ad4.z, ad4.w};
    float asrcn[HH] = {an4.x, an4.y, an4.z, an4.w};

    // phase A: logits, running max, sum of ale
    float lmx[HH] = {-1e30f, -1e30f, -1e30f, -1e30f};
    float lsa[HH] = {0, 0, 0, 0};
    for (int j = tid; j < deg; j += 128) {
        int e = g_eperm[st + j];
        int s = src[e];
        float4 al4 = *(const float4*)(g_ale + (size_t)e * HH);
        float4 as4 = *(const float4*)(g_alsrc + (size_t)s * HH);
        float l0 = lrelu(as4.x + adst[0] + al4.x);
        float l1 = lrelu(as4.y + adst[1] + al4.y);
        float l2 = lrelu(as4.z + adst[2] + al4.z);
        float l3 = lrelu(as4.w + adst[3] + al4.w);
        lsa[0] += al4.x; lsa[1] += al4.y; lsa[2] += al4.z; lsa[3] += al4.w;
        lmx[0] = fmaxf(lmx[0], l0); lmx[1] = fmaxf(lmx[1], l1);
        lmx[2] = fmaxf(lmx[2], l2); lmx[3] = fmaxf(lmx[3], l3);
        if (cached) {
            ss[j] = s;
            sw[0][j] = l0; sw[1][j] = l1; sw[2][j] = l2; sw[3][j] = l3;
        }
    }
#pragma unroll
    for (int h = 0; h < HH; h++)
#pragma unroll
        for (int o = 16; o; o >>= 1) {
            lmx[h] = fmaxf(lmx[h], __shfl_xor_sync(0xffffffffu, lmx[h], o));
            lsa[h] += __shfl_xor_sync(0xffffffffu, lsa[h], o);
        }
    if (lane == 0) {
#pragma unroll
        for (int h = 0; h < HH; h++) { red[wrp * 8 + h] = lmx[h]; red[wrp * 8 + 4 + h] = lsa[h]; }
    }
    __syncthreads();
    if (tid == 0) {
        float inv = 1.f / (float)(deg > 0 ? deg : 1);
#pragma unroll
        for (int h = 0; h < HH; h++) {
            float m = fmaxf(fmaxf(red[h], red[8 + h]), fmaxf(red[16 + h], red[24 + h]));
            float sa = red[4 + h] + red[12 + h] + red[20 + h] + red[28 + h];
            float llog = lrelu(asrcn[h] + adst[h] + sa * inv);
            m = fmaxf(m, llog);
            bc[h] = m;
            bc[4 + h] = expf(llog - m);     // self-loop exp weight
        }
    }
    __syncthreads();
    float mx[HH] = {bc[0], bc[1], bc[2], bc[3]};

    // phase exp
    float lse[HH] = {0, 0, 0, 0};
    for (int j = tid; j < deg; j += 128) {
        float l[HH];
        int e = -1;
        if (cached) {
#pragma unroll
            for (int h = 0; h < HH; h++) l[h] = sw[h][j];
        } else {
            e = g_eperm[st + j];
            int s = src[e];
            float4 al4 = *(const float4*)(g_ale + (size_t)e * HH);
            float4 as4 = *(const float4*)(g_alsrc + (size_t)s * HH);
            l[0] = lrelu(as4.x + adst[0] + al4.x);
            l[1] = lrelu(as4.y + adst[1] + al4.y);
            l[2] = lrelu(as4.z + adst[2] + al4.z);
            l[3] = lrelu(as4.w + adst[3] + al4.w);
        }
        float w[HH];
#pragma unroll
        for (int h = 0; h < HH; h++) { w[h] = expf(l[h] - mx[h]); lse[h] += w[h]; }
        if (cached) {
#pragma unroll
            for (int h = 0; h < HH; h++) sw[h][j] = w[h];
        } else {
            *(float4*)(g_expw + (size_t)e * HH) = make_float4(w[0], w[1], w[2], w[3]);
        }
    }
#pragma unroll
    for (int h = 0; h < HH; h++)
#pragma unroll
        for (int o = 16; o; o >>= 1) lse[h] += __shfl_xor_sync(0xffffffffu, lse[h], o);
    if (lane == 0) {
#pragma unroll
        for (int h = 0; h < HH; h++) red[wrp * 8 + h] = lse[h];
    }
    __syncthreads();
    if (tid == 0) {
#pragma unroll
        for (int h = 0; h < HH; h++) {
            float s = red[h] + red[8 + h] + red[16 + h] + red[24 + h];
            bc[8 + h] = 1.f / (s + bc[4 + h] + 1e-16f);
        }
    }
    __syncthreads();

    // phase B: aggregate x[src] with weights (threads = channels)
    float acc[R][HH];
#pragma unroll
    for (int r = 0; r < R; r++)
#pragma unroll
        for (int h = 0; h < HH; h++) acc[r][h] = 0.f;

    for (int j = 0; j < deg; j++) {
        int s;
        float w0, w1, w2, w3;
        if (cached) {
            s = ss[j];
            w0 = sw[0][j]; w1 = sw[1][j]; w2 = sw[2][j]; w3 = sw[3][j];
        } else {
            int e = g_eperm[st + j];
            s = src[e];
            float4 w4 = *(const float4*)(g_expw + (size_t)e * HH);
            w0 = w4.x; w1 = w4.y; w2 = w4.z; w3 = w4.w;
        }
        const float* xrow = x + (size_t)s * KD;
#pragma unroll
        for (int r = 0; r < R; r++) {
            float xv = xrow[tid + r * 128];
            acc[r][0] += w0 * xv; acc[r][1] += w1 * xv;
            acc[r][2] += w2 * xv; acc[r][3] += w3 * xv;
        }
    }
    // self loop
    {
        const float* xrow = x + (size_t)n * KD;
#pragma unroll
        for (int r = 0; r < R; r++) {
            float xv = xrow[tid + r * 128];
            acc[r][0] += bc[4] * xv; acc[r][1] += bc[5] * xv;
            acc[r][2] += bc[6] * xv; acc[r][3] += bc[7] * xv;
        }
    }
    float* yrow = y + (size_t)n * (HH * KD);
#pragma unroll
    for (int r = 0; r < R; r++)
#pragma unroll
        for (int h = 0; h < HH; h++)
            yrow[h * KD + r * 128 + tid] = acc[r][h] * bc[8 + h];
}

// ---------------- GEMM: C[M,Ncol] = A[M,K]@B[K,Ncol] + bias, ELU ----------------
// BM=128, BN=64, BK=16, 256 threads, 8x4 micro-tile, double-buffered smem.
#define BM 128
#define BN 64
#define BK 16
__global__ void __launch_bounds__(256) k_gemm(const float* __restrict__ A,
                                              const float* __restrict__ B,
                                              const float* __restrict__ bias,
                                              float* __restrict__ C,
                                              int M, int K, int Ncol) {
    __shared__ float As[2][BK][BM];
    __shared__ float Bs[2][BK][BN];
    int tid = threadIdx.x;
    int tx = tid & 15;            // col group 0..15 -> cols tx*4..+3
    int ty = tid >> 4;            // row group 0..15 -> rows ty*8..+7
    int row0 = blockIdx.y * BM, col0 = blockIdx.x * BN;

    // A tile loaders: 128 rows x 4 float4 = 512 float4; 2 per thread.
    int ar = tid >> 1;            // 0..127
    int af = (tid & 1) * 2;       // float4 index 0 or 2 (covers 0,1 / 2,3)
    int arow = row0 + ar;
    bool arok = (arow < M);
    // B tile loaders: 16 rows x 16 float4 = 256 float4; 1 per thread.
    int bk = tid >> 4;            // 0..15
    int bc = (tid & 15) * 4;      // 0..60

    float acc[8][4];
#pragma unroll
    for (int i = 0; i < 8; i++)
#pragma unroll
        for (int j = 0; j < 4; j++) acc[i][j] = 0.f;

    int nsteps = K / BK;
    const float* Arow = A + (size_t)arow * K;

    float4 av0, av1, bv;
    av0 = arok ? *(const float4*)(Arow + af * 4)     : make_float4(0, 0, 0, 0);
    av1 = arok ? *(const float4*)(Arow + af * 4 + 4) : make_float4(0, 0, 0, 0);
    bv  = *(const float4*)(B + (size_t)bk * Ncol + col0 + bc);
    As[0][af * 4 + 0][ar] = av0.x; As[0][af * 4 + 1][ar] = av0.y;
    As[0][af * 4 + 2][ar] = av0.z; As[0][af * 4 + 3][ar] = av0.w;
    As[0][af * 4 + 4][ar] = av1.x; As[0][af * 4 + 5][ar] = av1.y;
    As[0][af * 4 + 6][ar] = av1.z; As[0][af * 4 + 7][ar] = av1.w;
    *(float4*)&Bs[0][bk][bc] = bv;
    __syncthreads();

    for (int s = 0; s < nsteps; s++) {
        int cur = s & 1, nxt = cur ^ 1;
        if (s + 1 < nsteps) {
            int k0 = (s + 1) * BK;
            av0 = arok ? *(const float4*)(Arow + k0 + af * 4)     : make_float4(0, 0, 0, 0);
            av1 = arok ? *(const float4*)(Arow + k0 + af * 4 + 4) : make_float4(0, 0, 0, 0);
            bv  = *(const float4*)(B + (size_t)(k0 + bk) * Ncol + col0 + bc);
        }
#pragma unroll
        for (int kk = 0; kk < BK; kk++) {
            float4 a0 = *(const float4*)&As[cur][kk][ty * 8];
            float4 a1 = *(const float4*)&As[cur][kk][ty * 8 + 4];
            float4 b4 = *(const float4*)&Bs[cur][kk][tx * 4];
            float a[8] = {a0.x, a0.y, a0.z, a0.w, a1.x, a1.y, a1.z, a1.w};
            float b[4] = {b4.x, b4.y, b4.z, b4.w};
#pragma unroll
            for (int i = 0; i < 8; i++)
#pragma unroll
                for (int j = 0; j < 4; j++) acc[i][j] += a[i] * b[j];
        }
        if (s + 1 < nsteps) {
            As[nxt][af * 4 + 0][ar] = av0.x; As[nxt][af * 4 + 1][ar] = av0.y;
            As[nxt][af * 4 + 2][ar] = av0.z; As[nxt][af * 4 + 3][ar] = av0.w;
            As[nxt][af * 4 + 4][ar] = av1.x; As[nxt][af * 4 + 5][ar] = av1.y;
            As[nxt][af * 4 + 6][ar] = av1.z; As[nxt][af * 4 + 7][ar] = av1.w;
            *(float4*)&Bs[nxt][bk][bc] = bv;
            __syncthreads();
        }
    }

    float bs[4];
#pragma unroll
    for (int j = 0; j < 4; j++) bs[j] = bias[col0 + tx * 4 + j];
#pragma unroll
    for (int i = 0; i < 8; i++) {
        int r = row0 + ty * 8 + i;
        if (r < M) {
            float4 o;
            float v0 = acc[i][0] + bs[0], v1 = acc[i][1] + bs[1];
            float v2 = acc[i][2] + bs[2], v3 = acc[i][3] + bs[3];
            o.x = v0 > 0.f ? v0 : expm1f(v0);
            o.y = v1 > 0.f ? v1 : expm1f(v1);
            o.z = v2 > 0.f ? v2 : expm1f(v2);
            o.w = v3 > 0.f ? v3 : expm1f(v3);
            *(float4*)(C + (size_t)r * Ncol + col0 + tx * 4) = o;
        }
    }
}

// ---------------- graph mean pooling ----------------
__global__ void k_gcnt(const int* __restrict__ batch) {
    int n = blockIdx.x * blockDim.x + threadIdx.x;
    if (n < NN) atomicAdd(&g_gcnt[batch[n]], 1);
}

__global__ void k_pool(const int* __restrict__ batch, const float* __restrict__ h,
                       float* __restrict__ out) {
    int n = blockIdx.x;
    int t = threadIdx.x;  // 128
    atomicAdd(&out[(size_t)batch[n] * 128 + t], h[(size_t)n * 128 + t]);
}

__global__ void k_pooldiv(float* __restrict__ out) {
    int i = blockIdx.x * blockDim.x + threadIdx.x;
    if (i < GG * 128) {
        int g = i / 128;
        int c = g_gcnt[g];
        out[i] /= (float)(c > 0 ? c : 1);
    }
}

// ---------------- launch ----------------
extern "C" void kernel_launch(void* const* d_in, const int* in_sizes, int n_in,
                              void* d_out, int out_size) {
    const float* x     = (const float*)d_in[0];
    const int*   ei    = (const int*)d_in[1];
    const float* eattr = (const float*)d_in[2];
    const int*   batch = (const int*)d_in[3];
    const int* src = ei;
    const int* dst = ei + EE;

    const float* W[3]  = {(const float*)d_in[4],  (const float*)d_in[10], (const float*)d_in[16]};
    const float* We[3] = {(const float*)d_in[5],  (const float*)d_in[11], (const float*)d_in[17]};
    const float* As[3] = {(const float*)d_in[6],  (const float*)d_in[12], (const float*)d_in[18]};
    const float* Ad[3] = {(const float*)d_in[7],  (const float*)d_in[13], (const float*)d_in[19]};
    const float* Ae[3] = {(const float*)d_in[8],  (const float*)d_in[14], (const float*)d_in[20]};
    const float* Bb[3] = {(const float*)d_in[9],  (const float*)d_in[15], (const float*)d_in[21]};
    (void)n_in; (void)in_sizes; (void)out_size;

    float* out = (float*)d_out;

    void *p_deg, *p_gcnt, *p_y, *p_hA, *p_hB, *p_ws;
    cudaGetSymbolAddress(&p_deg, g_deg);
    cudaGetSymbolAddress(&p_gcnt, g_gcnt);
    cudaGetSymbolAddress(&p_y, g_y);
    cudaGetSymbolAddress(&p_hA, g_hA);
    cudaGetSymbolAddress(&p_hB, g_hB);
    cudaGetSymbolAddress(&p_ws, g_wstack);
    float* y  = (float*)p_y;
    float* hA = (float*)p_hA;
    float* hB = (float*)p_hB;
    float* ws = (float*)p_ws;

    cudaMemsetAsync(p_deg, 0, NN * sizeof(int));
    cudaMemsetAsync(p_gcnt, 0, GG * sizeof(int));
    cudaMemsetAsync(out, 0, (size_t)GG * 128 * sizeof(float));

    // CSR build
    k_deg<<<(EE + 255) / 256, 256>>>(dst);
    k_scan<<<1, 1024>>>();
    k_scatter<<<(EE + 255) / 256, 256>>>(dst);

    const int Kdim[3] = {128, 128, 256};   // input dim per layer
    const int Cdim[3] = {128, 256, 128};   // output dim per layer
    const float* lin[3]  = {x, hA, hB};
    float*       lout[3] = {hA, hB, hA};

    for (int l = 0; l < 3; l++) {
        int Kd = Kdim[l], Cd = Cdim[l];
        int wa_blocks = (Kd * HH + 7) / 8;
        k_prep<<<wa_blocks + 16 + 64, 256>>>(W[l], We[l], As[l], Ad[l], Ae[l],
                                             Kd, Cd, wa_blocks);
        k_ale<<<(EE + 127) / 128, 128>>>(eattr);
        k_al<<<(NN + 7) / 8, 256>>>(lin[l], Kd);
        if (Kd == 128)
            k_fsa<128><<<NN, 128>>>(src, lin[l], y);
        else
            k_fsa<256><<<NN, 128>>>(src, lin[l], y);
        int Kg = HH * Kd;
        dim3 gg(Cd / BN, (NN + BM - 1) / BM);
        k_gemm<<<gg, 256>>>(y, ws, Bb[l], lout[l], NN, Kg, Cd);
    }

    k_gcnt<<<(NN + 255) / 256, 256>>>(batch);
    k_pool<<<NN, 128>>>(batch, hA, out);
    k_pooldiv<<<(GG * 128 + 255) / 256, 256>>>(out);
}

// round 6
// speedup vs baseline: 1.7280x; 1.5216x over previous
#include <cuda_runtime.h>
#include <cuda_bf16.h>
#include <math.h>
#include <stdint.h>

#define NN 10000
#define EE 160000
#define GG 64
#define HH 4
#define EDIM 32

// ---------------- static scratch ----------------
__device__ int   g_deg[NN];
__device__ int   g_rowptr[NN + 1];
__device__ int   g_cursor[NN];
__device__ int   g_eperm[EE];
__device__ __nv_bfloat16 g_yhi[(size_t)NN * 1024];
__device__ __nv_bfloat16 g_ylo[(size_t)NN * 1024];
__device__ float g_hA[(size_t)NN * 256];
__device__ float g_hB[(size_t)NN * 256];
__device__ float g_alsrc[NN * HH];
__device__ float g_aldst[NN * HH];
__device__ float g_ale[(size_t)3 * EE * HH];
__device__ float g_expw[(size_t)EE * HH];     // fallback (deg > 512)
__device__ float g_M[3 * EDIM * HH];
__device__ float g_Was[3 * 1024];             // per-layer! [l][h*KD+k]
__device__ float g_Wad[3 * 1024];
// per-layer transposed/split weights, B[n, kg] K-major: sizes 65536,131072,131072
__device__ __nv_bfloat16 g_bhi[327680];
__device__ __nv_bfloat16 g_blo[327680];
__device__ int   g_gcnt[GG];

// ---------------- generic PTX helpers (compute_103-safe) ----------------
__device__ __forceinline__ uint32_t smem_u32(const void* p) {
    uint32_t a;
    asm("{ .reg .u64 t; cvta.to.shared.u64 t, %1; cvt.u32.u64 %0, t; }"
        : "=r"(a) : "l"(p));
    return a;
}
__device__ __forceinline__ void cp_async16(uint32_t saddr, const void* gptr) {
    asm volatile("cp.async.ca.shared.global [%0], [%1], 16;"
                 :: "r"(saddr), "l"(gptr) : "memory");
}
__device__ __forceinline__ void cp_commit() {
    asm volatile("cp.async.commit_group;" ::: "memory");
}
template <int N>
__device__ __forceinline__ void cp_wait() {
    asm volatile("cp.async.wait_group %0;" :: "n"(N) : "memory");
}
__device__ __forceinline__ void ldsm_x4(uint32_t* r, uint32_t addr) {
    asm volatile("ldmatrix.sync.aligned.m8n8.x4.shared.b16 {%0,%1,%2,%3}, [%4];"
                 : "=r"(r[0]), "=r"(r[1]), "=r"(r[2]), "=r"(r[3]) : "r"(addr));
}
__device__ __forceinline__ void mma_bf16(float* d, const uint32_t* a,
                                         uint32_t b0, uint32_t b1) {
    asm volatile(
        "mma.sync.aligned.m16n8k16.row.col.f32.bf16.bf16.f32 "
        "{%0,%1,%2,%3}, {%4,%5,%6,%7}, {%8,%9}, {%0,%1,%2,%3};"
        : "+f"(d[0]), "+f"(d[1]), "+f"(d[2]), "+f"(d[3])
        : "r"(a[0]), "r"(a[1]), "r"(a[2]), "r"(a[3]), "r"(b0), "r"(b1));
}

// ---------------- CSR build ----------------
__global__ void k_deg(const int* __restrict__ dst) {
    int e = blockIdx.x * blockDim.x + threadIdx.x;
    if (e < EE) atomicAdd(&g_deg[dst[e]], 1);
}

__global__ void k_scan() {
    __shared__ int sh[1024];
    __shared__ int carry;
    int tid = threadIdx.x;
    if (tid == 0) { carry = 0; g_rowptr[0] = 0; }
    __syncthreads();
    for (int base = 0; base < NN; base += 1024) {
        int i = base + tid;
        int v = (i < NN) ? g_deg[i] : 0;
        sh[tid] = v;
        __syncthreads();
        for (int off = 1; off < 1024; off <<= 1) {
            int t = (tid >= off) ? sh[tid - off] : 0;
            __syncthreads();
            sh[tid] += t;
            __syncthreads();
        }
        int inc = sh[tid];
        int cl = carry;
        if (i < NN) {
            g_rowptr[i + 1] = cl + inc;
            g_cursor[i] = cl + inc - v;
        }
        __syncthreads();
        if (tid == 0) carry = cl + sh[1023];
        __syncthreads();
    }
}

__global__ void k_scatter(const int* __restrict__ dst) {
    int e = blockIdx.x * blockDim.x + threadIdx.x;
    if (e < EE) {
        int p = atomicAdd(&g_cursor[dst[e]], 1);
        g_eperm[p] = e;
    }
}

// ---------------- weight preprocessing: Wa (warp/(k,h)) + M (warp/(d,h)) ----------------
__global__ void __launch_bounds__(256) k_prep(const float* __restrict__ W,
                                              const float* __restrict__ We,
                                              const float* __restrict__ a_s,
                                              const float* __restrict__ a_d,
                                              const float* __restrict__ a_e,
                                              int KD, int C, int wa_blocks, int layer) {
    int b = blockIdx.x;
    int lane = threadIdx.x & 31;
    int wrp = threadIdx.x >> 5;
    if (b < wa_blocks) {
        int idx = b * 8 + wrp;
        if (idx < KD * HH) {
            int k = idx / HH, h = idx % HH;
            const float* wrow = W + (size_t)k * HH * C + h * C;
            const float* as = a_s + h * C;
            const float* ad = a_d + h * C;
            float s = 0.f, d = 0.f;
            for (int c = lane; c < C; c += 32) {
                float w = wrow[c];
                s += w * as[c];
                d += w * ad[c];
            }
#pragma unroll
            for (int o = 16; o; o >>= 1) {
                s += __shfl_xor_sync(0xffffffffu, s, o);
                d += __shfl_xor_sync(0xffffffffu, d, o);
            }
            if (lane == 0) {
                g_Was[layer * 1024 + h * KD + k] = s;
                g_Wad[layer * 1024 + h * KD + k] = d;
            }
        }
    } else {
        int idx = (b - wa_blocks) * 8 + wrp;
        if (idx < EDIM * HH) {
            int d = idx / HH, h = idx % HH;
            const float* werow = We + (size_t)d * HH * C + h * C;
            const float* ae = a_e + h * C;
            float s = 0.f;
            for (int c = lane; c < C; c += 32) s += werow[c] * ae[c];
#pragma unroll
            for (int o = 16; o; o >>= 1) s += __shfl_xor_sync(0xffffffffu, s, o);
            if (lane == 0) g_M[layer * EDIM * HH + d * HH + h] = s;
        }
    }
}

// ---------------- weight transpose+split: B[n, kg] = W[k', h*C+n] * 0.25 ----------------
__global__ void k_trans(const float* __restrict__ W, int KD, int CD,
                        __nv_bfloat16* __restrict__ bhi, __nv_bfloat16* __restrict__ blo) {
    __shared__ float s[32][33];
    int KG = HH * KD;
    int kg0 = blockIdx.x * 32;
    int n0 = blockIdx.y * 32;
    int tx = threadIdx.x, ty = threadIdx.y;   // (32, 8)
#pragma unroll
    for (int i = 0; i < 4; i++) {
        int kg = kg0 + ty * 4 + i;
        int k = kg % KD, h = kg / KD;
        s[ty * 4 + i][tx] = W[(size_t)k * (HH * CD) + h * CD + n0 + tx] * 0.25f;
    }
    __syncthreads();
#pragma unroll
    for (int i = 0; i < 4; i++) {
        int r = ty * 4 + i;                    // n_local
        float v = s[tx][r];
        __nv_bfloat16 hi = __float2bfloat16(v);
        float rem = v - __bfloat162float(hi);
        size_t o = (size_t)(n0 + r) * KG + kg0 + tx;
        bhi[o] = hi;
        blo[o] = __float2bfloat16(rem);
    }
}

// ---------------- per-edge attention logits, all 3 layers in one pass ----------------
__global__ void k_ale_all(const float* __restrict__ eattr) {
    __shared__ float Ms[3 * EDIM * HH];
    for (int i = threadIdx.x; i < 3 * EDIM * HH; i += blockDim.x) Ms[i] = g_M[i];
    __syncthreads();
    int e = blockIdx.x * blockDim.x + threadIdx.x;
    if (e >= EE) return;
    float a[3][HH];
#pragma unroll
    for (int l = 0; l < 3; l++)
#pragma unroll
        for (int h = 0; h < HH; h++) a[l][h] = 0.f;
    const float4* ep = (const float4*)(eattr + (size_t)e * EDIM);
#pragma unroll
    for (int q = 0; q < EDIM / 4; q++) {
        float4 v = ep[q];
        int d = q * 4;
#pragma unroll
        for (int l = 0; l < 3; l++) {
            const float* M = Ms + l * EDIM * HH;
#pragma unroll
            for (int h = 0; h < HH; h++) {
                a[l][h] += v.x * M[(d + 0) * HH + h] + v.y * M[(d + 1) * HH + h]
                         + v.z * M[(d + 2) * HH + h] + v.w * M[(d + 3) * HH + h];
            }
        }
    }
#pragma unroll
    for (int l = 0; l < 3; l++)
        *(float4*)(g_ale + (size_t)l * EE * HH + (size_t)e * HH)
            = make_float4(a[l][0], a[l][1], a[l][2], a[l][3]);
}

// ---------------- per-node attention coefficients: al = x @ Wa ----------------
__global__ void k_al(const float* __restrict__ x, const float* __restrict__ Was_g,
                     const float* __restrict__ Wad_g, int KD) {
    __shared__ float Was[HH * 256];
    __shared__ float Wad[HH * 256];
    int tid = threadIdx.x;
    for (int i = tid; i < HH * KD; i += 256) { Was[i] = Was_g[i]; Wad[i] = Wad_g[i]; }
    __syncthreads();
    int lane = tid & 31;
    int n = blockIdx.x * 8 + (tid >> 5);
    if (n >= NN) return;
    float s[HH] = {0, 0, 0, 0}, d[HH] = {0, 0, 0, 0};
    const float* xrow = x + (size_t)n * KD;
    for (int k = lane; k < KD; k += 32) {
        float xv = xrow[k];
#pragma unroll
        for (int h = 0; h < HH; h++) {
            s[h] += xv * Was[h * KD + k];
            d[h] += xv * Wad[h * KD + k];
        }
    }
#pragma unroll
    for (int h = 0; h < HH; h++)
#pragma unroll
        for (int o = 16; o; o >>= 1) {
            s[h] += __shfl_xor_sync(0xffffffffu, s[h], o);
            d[h] += __shfl_xor_sync(0xffffffffu, d[h], o);
        }
    if (lane == 0) {
        *(float4*)(g_alsrc + n * HH) = make_float4(s[0], s[1], s[2], s[3]);
        *(float4*)(g_aldst + n * HH) = make_float4(d[0], d[1], d[2], d[3]);
    }
}

// ---------------- fused segment-softmax + x-space aggregation -> bf16 splits ----------------
__device__ __forceinline__ float lrelu(float v) { return v >= 0.f ? v : 0.2f * v; }

template <int KD>
__global__ void __launch_bounds__(128) k_fsa(const int* __restrict__ src,
                                             const float* __restrict__ x,
                                             const float* __restrict__ ale,
                                             __nv_bfloat16* __restrict__ yhi,
                                             __nv_bfloat16* __restrict__ ylo) {
    constexpr int CAP = 512;
    constexpr int R = KD / 128;
    constexpr int KG = HH * KD;
    __shared__ int   ss[CAP];
    __shared__ float sw[HH][CAP];
    __shared__ float red[32];
    __shared__ float bc[12];

    int n = blockIdx.x;
    int tid = threadIdx.x, lane = tid & 31, wrp = tid >> 5;
    int st = g_rowptr[n], en = g_rowptr[n + 1];
    int deg = en - st;
    bool cached = (deg <= CAP);

    float4 ad4 = *(const float4*)(g_aldst + n * HH);
    float4 an4 = *(const float4*)(g_alsrc + n * HH);
    float adst[HH] = {ad4.x, ad4.y, ad4.z, ad4.w};
    float asrcn[HH] = {an4.x, an4.y, an4.z, an4.w};

    float lmx[HH] = {-1e30f, -1e30f, -1e30f, -1e30f};
    float lsa[HH] = {0, 0, 0, 0};
    for (int j = tid; j < deg; j += 128) {
        int e = g_eperm[st + j];
        int s = src[e];
        float4 al4 = *(const float4*)(ale + (size_t)e * HH);
        float4 as4 = *(const float4*)(g_alsrc + (size_t)s * HH);
        float l0 = lrelu(as4.x + adst[0] + al4.x);
        float l1 = lrelu(as4.y + adst[1] + al4.y);
        float l2 = lrelu(as4.z + adst[2] + al4.z);
        float l3 = lrelu(as4.w + adst[3] + al4.w);
        lsa[0] += al4.x; lsa[1] += al4.y; lsa[2] += al4.z; lsa[3] += al4.w;
        lmx[0] = fmaxf(lmx[0], l0); lmx[1] = fmaxf(lmx[1], l1);
        lmx[2] = fmaxf(lmx[2], l2); lmx[3] = fmaxf(lmx[3], l3);
        if (cached) {
            ss[j] = s;
            sw[0][j] = l0; sw[1][j] = l1; sw[2][j] = l2; sw[3][j] = l3;
        }
    }
#pragma unroll
    for (int h = 0; h < HH; h++)
#pragma unroll
        for (int o = 16; o; o >>= 1) {
            lmx[h] = fmaxf(lmx[h], __shfl_xor_sync(0xffffffffu, lmx[h], o));
            lsa[h] += __shfl_xor_sync(0xffffffffu, lsa[h], o);
        }
    if (lane == 0) {
#pragma unroll
        for (int h = 0; h < HH; h++) { red[wrp * 8 + h] = lmx[h]; red[wrp * 8 + 4 + h] = lsa[h]; }
    }
    __syncthreads();
    if (tid == 0) {
        float inv = 1.f / (float)(deg > 0 ? deg : 1);
#pragma unroll
        for (int h = 0; h < HH; h++) {
            float m = fmaxf(fmaxf(red[h], red[8 + h]), fmaxf(red[16 + h], red[24 + h]));
            float sa = red[4 + h] + red[12 + h] + red[20 + h] + red[28 + h];
            float llog = lrelu(asrcn[h] + adst[h] + sa * inv);
            m = fmaxf(m, llog);
            bc[h] = m;
            bc[4 + h] = expf(llog - m);
        }
    }
    __syncthreads();
    float mx[HH] = {bc[0], bc[1], bc[2], bc[3]};

    float lse[HH] = {0, 0, 0, 0};
    for (int j = tid; j < deg; j += 128) {
        float l[HH];
        int e = -1;
        if (cached) {
#pragma unroll
            for (int h = 0; h < HH; h++) l[h] = sw[h][j];
        } else {
            e = g_eperm[st + j];
            int s = src[e];
            float4 al4 = *(const float4*)(ale + (size_t)e * HH);
            float4 as4 = *(const float4*)(g_alsrc + (size_t)s * HH);
            l[0] = lrelu(as4.x + adst[0] + al4.x);
            l[1] = lrelu(as4.y + adst[1] + al4.y);
            l[2] = lrelu(as4.z + adst[2] + al4.z);
            l[3] = lrelu(as4.w + adst[3] + al4.w);
        }
        float w[HH];
#pragma unroll
        for (int h = 0; h < HH; h++) { w[h] = expf(l[h] - mx[h]); lse[h] += w[h]; }
        if (cached) {
#pragma unroll
            for (int h = 0; h < HH; h++) sw[h][j] = w[h];
        } else {
            *(float4*)(g_expw + (size_t)e * HH) = make_float4(w[0], w[1], w[2], w[3]);
        }
    }
#pragma unroll
    for (int h = 0; h < HH; h++)
#pragma unroll
        for (int o = 16; o; o >>= 1) lse[h] += __shfl_xor_sync(0xffffffffu, lse[h], o);
    if (lane == 0) {
#pragma unroll
        for (int h = 0; h < HH; h++) red[wrp * 8 + h] = lse[h];
    }
    __syncthreads();
    if (tid == 0) {
#pragma unroll
        for (int h = 0; h < HH; h++) {
            float s = red[h] + red[8 + h] + red[16 + h] + red[24 + h];
            bc[8 + h] = 1.f / (s + bc[4 + h] + 1e-16f);
        }
    }
    __syncthreads();

    float acc[R][HH];
#pragma unroll
    for (int r = 0; r < R; r++)
#pragma unroll
        for (int h = 0; h < HH; h++) acc[r][h] = 0.f;

    for (int j = 0; j < deg; j++) {
        int s;
        float w0, w1, w2, w3;
        if (cached) {
            s = ss[j];
            w0 = sw[0][j]; w1 = sw[1][j]; w2 = sw[2][j]; w3 = sw[3][j];
        } else {
            int e = g_eperm[st + j];
            s = src[e];
            float4 w4 = *(const float4*)(g_expw + (size_t)e * HH);
            w0 = w4.x; w1 = w4.y; w2 = w4.z; w3 = w4.w;
        }
        const float* xrow = x + (size_t)s * KD;
#pragma unroll
        for (int r = 0; r < R; r++) {
            float xv = xrow[tid + r * 128];
            acc[r][0] += w0 * xv; acc[r][1] += w1 * xv;
            acc[r][2] += w2 * xv; acc[r][3] += w3 * xv;
        }
    }
    {
        const float* xrow = x + (size_t)n * KD;
#pragma unroll
        for (int r = 0; r < R; r++) {
            float xv = xrow[tid + r * 128];
            acc[r][0] += bc[4] * xv; acc[r][1] += bc[5] * xv;
            acc[r][2] += bc[6] * xv; acc[r][3] += bc[7] * xv;
        }
    }
#pragma unroll
    for (int r = 0; r < R; r++)
#pragma unroll
        for (int h = 0; h < HH; h++) {
            float v = acc[r][h] * bc[8 + h];
            __nv_bfloat16 hi = __float2bfloat16(v);
            float rem = v - __bfloat162float(hi);
            size_t o = (size_t)n * KG + h * KD + r * 128 + tid;
            yhi[o] = hi;
            ylo[o] = __float2bfloat16(rem);
        }
}

// ---------------- warp-MMA bf16 split GEMM: hout = ELU(y @ B^T + bias) ----------------
// A[m,kg] hi/lo bf16, B[n,kg] hi/lo bf16, fp32 accum, 3-pass error correction.
// BM=64, BN=128, BK=32; 256 threads = 8 warps (2 x 4); warp tile 32x32.
// Smem rows padded to 40 bf16 (80B) for conflict-free ldmatrix; cp.async double-buffered.
template <int KG, int CD>
__global__ void __launch_bounds__(256) k_hgemm(const __nv_bfloat16* __restrict__ yhi,
                                               const __nv_bfloat16* __restrict__ ylo,
                                               const __nv_bfloat16* __restrict__ bhi,
                                               const __nv_bfloat16* __restrict__ blo,
                                               const float* __restrict__ bias,
                                               float* __restrict__ hout) {
    constexpr int NC = KG / 32;
    constexpr int A_HI = 0;
    constexpr int A_LO = 5120;      // 64*80
    constexpr int B_HI = 10240;
    constexpr int B_LO = 20480;     // B_HI + 128*80
    constexpr int STAGE = 30720;
    extern __shared__ char smem[];

    int tid = threadIdx.x;
    int lane = tid & 31, wid = tid >> 5;
    int warp_m = wid >> 2, warp_n = wid & 3;
    int m0 = blockIdx.x * 64;
    int n0 = blockIdx.y * 128;
    uint32_t sbase0 = smem_u32(smem);

    float acc[2][4][4];
#pragma unroll
    for (int i = 0; i < 2; i++)
#pragma unroll
        for (int j = 0; j < 4; j++)
#pragma unroll
            for (int k = 0; k < 4; k++) acc[i][j][k] = 0.f;

    // ---- stage loader ----
    auto load_stage = [&](int kc, int buf) {
        uint32_t sb = sbase0 + buf * STAGE;
        int kg0 = kc * 32;
        // A: 512 16B chunks (hi 256, lo 256), 2 per thread
#pragma unroll
        for (int i = 0; i < 2; i++) {
            int idx = i * 256 + tid;
            int half = idx >> 8;
            int rem = idx & 255;
            int r = rem >> 2, ch = rem & 3;
            int row = m0 + r;
            if (row >= NN) row = NN - 1;   // clamp (result rows >= NN are discarded)
            const __nv_bfloat16* gp = (half ? ylo : yhi) + (size_t)row * KG + kg0 + ch * 8;
            cp_async16(sb + (half ? A_LO : A_HI) + r * 80 + ch * 16, gp);
        }
        // B: 1024 16B chunks (hi 512, lo 512), 4 per thread
#pragma unroll
        for (int i = 0; i < 4; i++) {
            int idx = i * 256 + tid;
            int half = idx >> 9;
            int rem = idx & 511;
            int r = rem >> 2, ch = rem & 3;
            const __nv_bfloat16* gp = (half ? blo : bhi) + (size_t)(n0 + r) * KG + kg0 + ch * 8;
            cp_async16(sb + (half ? B_LO : B_HI) + r * 80 + ch * 16, gp);
        }
        cp_commit();
    };

    load_stage(0, 0);

    for (int kc = 0; kc < NC; kc++) {
        int buf = kc & 1;
        if (kc + 1 < NC) { load_stage(kc + 1, buf ^ 1); cp_wait<1>(); }
        else             { cp_wait<0>(); }
        __syncthreads();

        uint32_t sb = sbase0 + buf * STAGE;
#pragma unroll
        for (int k16 = 0; k16 < 2; k16++) {
            // A fragments (hi/lo), 2 m-atoms each
            uint32_t ah[2][4], al_[2][4];
#pragma unroll
            for (int ma = 0; ma < 2; ma++) {
                int row = warp_m * 32 + ma * 16 + (lane & 7) + ((lane >> 3) & 1) * 8;
                int chunk = lane >> 4;
                uint32_t addr = sb + A_HI + row * 80 + k16 * 32 + chunk * 16;
                ldsm_x4(ah[ma], addr);
                ldsm_x4(al_[ma], addr + (A_LO - A_HI));
            }
            // B fragments (hi/lo), 2 n16-groups -> 4 n8 atoms
            uint32_t bh[2][4], bl[2][4];
#pragma unroll
            for (int g = 0; g < 2; g++) {
                int row = warp_n * 32 + g * 16 + (lane & 7) + ((lane >> 4) & 1) * 8;
                int chunk = (lane >> 3) & 1;
                uint32_t addr = sb + B_HI + row * 80 + k16 * 32 + chunk * 16;
                ldsm_x4(bh[g], addr);
                ldsm_x4(bl[g], addr + (B_LO - B_HI));
            }
#pragma unroll
            for (int ma = 0; ma < 2; ma++)
#pragma unroll
                for (int na = 0; na < 4; na++) {
                    int g = na >> 1, s = (na & 1) * 2;
                    mma_bf16(acc[ma][na], ah[ma], bh[g][s], bh[g][s + 1]);
                    mma_bf16(acc[ma][na], ah[ma], bl[g][s], bl[g][s + 1]);
                    mma_bf16(acc[ma][na], al_[ma], bh[g][s], bh[g][s + 1]);
                }
        }
        __syncthreads();
    }

    // ---- epilogue: bias + ELU ----
#pragma unroll
    for (int ma = 0; ma < 2; ma++) {
        int row = m0 + warp_m * 32 + ma * 16 + (lane >> 2);
#pragma unroll
        for (int na = 0; na < 4; na++) {
            int col = n0 + warp_n * 32 + na * 8 + (lane & 3) * 2;
            float b0 = bias[col], b1 = bias[col + 1];
            if (row < NN) {
                float v0 = acc[ma][na][0] + b0;
                float v1 = acc[ma][na][1] + b1;
                float2 o;
                o.x = v0 > 0.f ? v0 : expm1f(v0);
                o.y = v1 > 0.f ? v1 : expm1f(v1);
                *(float2*)(hout + (size_t)row * CD + col) = o;
            }
            if (row + 8 < NN) {
                float v2 = acc[ma][na][2] + b0;
                float v3 = acc[ma][na][3] + b1;
                float2 o;
                o.x = v2 > 0.f ? v2 : expm1f(v2);
                o.y = v3 > 0.f ? v3 : expm1f(v3);
                *(float2*)(hout + (size_t)(row + 8) * CD + col) = o;
            }
        }
    }
}

// ---------------- graph mean pooling ----------------
__global__ void k_gcnt(const int* __restrict__ batch) {
    int n = blockIdx.x * blockDim.x + threadIdx.x;
    if (n < NN) atomicAdd(&g_gcnt[batch[n]], 1);
}

__global__ void k_pool(const int* __restrict__ batch, const float* __restrict__ h,
                       float* __restrict__ out) {
    int n = blockIdx.x;
    int t = threadIdx.x;
    atomicAdd(&out[(size_t)batch[n] * 128 + t], h[(size_t)n * 128 + t]);
}

__global__ void k_pooldiv(float* __restrict__ out) {
    int i = blockIdx.x * blockDim.x + threadIdx.x;
    if (i < GG * 128) {
        int g = i / 128;
        int c = g_gcnt[g];
        out[i] /= (float)(c > 0 ? c : 1);
    }
}

// ---------------- launch ----------------
extern "C" void kernel_launch(void* const* d_in, const int* in_sizes, int n_in,
                              void* d_out, int out_size) {
    const float* x     = (const float*)d_in[0];
    const int*   ei    = (const int*)d_in[1];
    const float* eattr = (const float*)d_in[2];
    const int*   batch = (const int*)d_in[3];
    const int* src = ei;
    const int* dst = ei + EE;

    const float* W[3]  = {(const float*)d_in[4],  (const float*)d_in[10], (const float*)d_in[16]};
    const float* We[3] = {(const float*)d_in[5],  (const float*)d_in[11], (const float*)d_in[17]};
    const float* As[3] = {(const float*)d_in[6],  (const float*)d_in[12], (const float*)d_in[18]};
    const float* Ad[3] = {(const float*)d_in[7],  (const float*)d_in[13], (const float*)d_in[19]};
    const float* Ae[3] = {(const float*)d_in[8],  (const float*)d_in[14], (const float*)d_in[20]};
    const float* Bb[3] = {(const float*)d_in[9],  (const float*)d_in[15], (const float*)d_in[21]};
    (void)n_in; (void)in_sizes; (void)out_size;

    float* out = (float*)d_out;

    void *p_deg, *p_gcnt, *p_yhi, *p_ylo, *p_hA, *p_hB, *p_bhi, *p_blo, *p_ale;
    void *p_was, *p_wad;
    cudaGetSymbolAddress(&p_deg, g_deg);
    cudaGetSymbolAddress(&p_gcnt, g_gcnt);
    cudaGetSymbolAddress(&p_yhi, g_yhi);
    cudaGetSymbolAddress(&p_ylo, g_ylo);
    cudaGetSymbolAddress(&p_hA, g_hA);
    cudaGetSymbolAddress(&p_hB, g_hB);
    cudaGetSymbolAddress(&p_bhi, g_bhi);
    cudaGetSymbolAddress(&p_blo, g_blo);
    cudaGetSymbolAddress(&p_ale, g_ale);
    cudaGetSymbolAddress(&p_was, g_Was);
    cudaGetSymbolAddress(&p_wad, g_Wad);
    __nv_bfloat16* yhi = (__nv_bfloat16*)p_yhi;
    __nv_bfloat16* ylo = (__nv_bfloat16*)p_ylo;
    float* hA = (float*)p_hA;
    float* hB = (float*)p_hB;
    __nv_bfloat16* bhi = (__nv_bfloat16*)p_bhi;
    __nv_bfloat16* blo = (__nv_bfloat16*)p_blo;
    float* ale = (float*)p_ale;
    float* wasp = (float*)p_was;
    float* wadp = (float*)p_wad;

    const int SMEM_BYTES = 61440;
    cudaFuncSetAttribute((const void*)k_hgemm<512, 128>,
                         cudaFuncAttributeMaxDynamicSharedMemorySize, SMEM_BYTES);
    cudaFuncSetAttribute((const void*)k_hgemm<512, 256>,
                         cudaFuncAttributeMaxDynamicSharedMemorySize, SMEM_BYTES);
    cudaFuncSetAttribute((const void*)k_hgemm<1024, 128>,
                         cudaFuncAttributeMaxDynamicSharedMemorySize, SMEM_BYTES);

    cudaMemsetAsync(p_deg, 0, NN * sizeof(int));
    cudaMemsetAsync(p_gcnt, 0, GG * sizeof(int));
    cudaMemsetAsync(out, 0, (size_t)GG * 128 * sizeof(float));

    // CSR build
    k_deg<<<(EE + 255) / 256, 256>>>(dst);
    k_scan<<<1, 1024>>>();
    k_scatter<<<(EE + 255) / 256, 256>>>(dst);

    const int Kdim[3] = {128, 128, 256};
    const int Cdim[3] = {128, 256, 128};
    const size_t boff[3] = {0, 65536, 196608};

    // upfront weight preprocessing for all layers (per-layer Was/Wad/M slots)
    for (int l = 0; l < 3; l++) {
        int Kd = Kdim[l], Cd = Cdim[l];
        int wa_blocks = (Kd * HH + 7) / 8;
        k_prep<<<wa_blocks + 16, 256>>>(W[l], We[l], As[l], Ad[l], Ae[l], Kd, Cd,
                                        wa_blocks, l);
        dim3 tg(HH * Kd / 32, Cd / 32);
        k_trans<<<tg, dim3(32, 8)>>>(W[l], Kd, Cd, bhi + boff[l], blo + boff[l]);
    }
    k_ale_all<<<(EE + 127) / 128, 128>>>(eattr);

    const float* lin[3]  = {x, hA, hB};
    float*       lout[3] = {hA, hB, hA};
    const int MB = (NN + 63) / 64;   // 157

    for (int l = 0; l < 3; l++) {
        int Kd = Kdim[l];
        k_al<<<(NN + 7) / 8, 256>>>(lin[l], wasp + l * 1024, wadp + l * 1024, Kd);
        if (Kd == 128)
            k_fsa<128><<<NN, 128>>>(src, lin[l], ale + (size_t)l * EE * HH, yhi, ylo);
        else
            k_fsa<256><<<NN, 128>>>(src, lin[l], ale + (size_t)l * EE * HH, yhi, ylo);
        if (l == 0)
            k_hgemm<512, 128><<<dim3(MB, 1), 256, SMEM_BYTES>>>(
                yhi, ylo, bhi + boff[0], blo + boff[0], Bb[0], lout[0]);
        else if (l == 1)
            k_hgemm<512, 256><<<dim3(MB, 2), 256, SMEM_BYTES>>>(
                yhi, ylo, bhi + boff[1], blo + boff[1], Bb[1], lout[1]);
        else
            k_hgemm<1024, 128><<<dim3(MB, 1), 256, SMEM_BYTES>>>(
                yhi, ylo, bhi + boff[2], blo + boff[2], Bb[2], lout[2]);
    }

    k_gcnt<<<(NN + 255) / 256, 256>>>(batch);
    k_pool<<<NN, 128>>>(batch, hA, out);
    k_pooldiv<<<(GG * 128 + 255) / 256, 256>>>(out);
}

// round 7
// speedup vs baseline: 2.0292x; 1.1743x over previous
#include <cuda_runtime.h>
#include <cuda_bf16.h>
#include <math.h>
#include <stdint.h>

#define NN 10000
#define EE 160000
#define GG 64
#define HH 4
#define EDIM 32

// ---------------- static scratch ----------------
__device__ int   g_deg[NN];
__device__ int   g_rowptr[NN + 1];
__device__ int   g_cursor[NN];
__device__ int   g_eperm[EE];
__device__ __nv_bfloat16 g_yhi[(size_t)NN * 1024];
__device__ __nv_bfloat16 g_ylo[(size_t)NN * 1024];
__device__ float g_hA[(size_t)NN * 256];
__device__ float g_hB[(size_t)NN * 256];
__device__ float g_alsrc[NN * HH];
__device__ float g_aldst[NN * HH];
__device__ float g_ale[(size_t)3 * EE * HH];
__device__ float g_expw[(size_t)EE * HH];     // fallback (deg > 512)
__device__ float g_M[3 * EDIM * HH];
__device__ float g_Was[3 * 1024];             // per-layer [l][h*KD+k]
__device__ float g_Wad[3 * 1024];
__device__ __nv_bfloat16 g_bhi[327680];
__device__ __nv_bfloat16 g_blo[327680];

// ---------------- generic PTX helpers (compute_103-safe) ----------------
__device__ __forceinline__ uint32_t smem_u32(const void* p) {
    uint32_t a;
    asm("{ .reg .u64 t; cvta.to.shared.u64 t, %1; cvt.u32.u64 %0, t; }"
        : "=r"(a) : "l"(p));
    return a;
}
__device__ __forceinline__ void cp_async16(uint32_t saddr, const void* gptr) {
    asm volatile("cp.async.ca.shared.global [%0], [%1], 16;"
                 :: "r"(saddr), "l"(gptr) : "memory");
}
__device__ __forceinline__ void cp_commit() {
    asm volatile("cp.async.commit_group;" ::: "memory");
}
template <int N>
__device__ __forceinline__ void cp_wait() {
    asm volatile("cp.async.wait_group %0;" :: "n"(N) : "memory");
}
__device__ __forceinline__ void ldsm_x4(uint32_t* r, uint32_t addr) {
    asm volatile("ldmatrix.sync.aligned.m8n8.x4.shared.b16 {%0,%1,%2,%3}, [%4];"
                 : "=r"(r[0]), "=r"(r[1]), "=r"(r[2]), "=r"(r[3]) : "r"(addr));
}
__device__ __forceinline__ void mma_bf16(float* d, const uint32_t* a,
                                         uint32_t b0, uint32_t b1) {
    asm volatile(
        "mma.sync.aligned.m16n8k16.row.col.f32.bf16.bf16.f32 "
        "{%0,%1,%2,%3}, {%4,%5,%6,%7}, {%8,%9}, {%0,%1,%2,%3};"
        : "+f"(d[0]), "+f"(d[1]), "+f"(d[2]), "+f"(d[3])
        : "r"(a[0]), "r"(a[1]), "r"(a[2]), "r"(a[3]), "r"(b0), "r"(b1));
}

// ---------------- CSR build ----------------
__global__ void k_deg(const int* __restrict__ dst) {
    int e = blockIdx.x * blockDim.x + threadIdx.x;
    if (e < EE) atomicAdd(&g_deg[dst[e]], 1);
}

__global__ void k_scan() {
    __shared__ int sh[1024];
    __shared__ int carry;
    int tid = threadIdx.x;
    if (tid == 0) { carry = 0; g_rowptr[0] = 0; }
    __syncthreads();
    for (int base = 0; base < NN; base += 1024) {
        int i = base + tid;
        int v = (i < NN) ? g_deg[i] : 0;
        sh[tid] = v;
        __syncthreads();
        for (int off = 1; off < 1024; off <<= 1) {
            int t = (tid >= off) ? sh[tid - off] : 0;
            __syncthreads();
            sh[tid] += t;
            __syncthreads();
        }
        int inc = sh[tid];
        int cl = carry;
        if (i < NN) {
            g_rowptr[i + 1] = cl + inc;
            g_cursor[i] = cl + inc - v;
        }
        __syncthreads();
        if (tid == 0) carry = cl + sh[1023];
        __syncthreads();
    }
}

// ---------------- region helpers for the fused setup kernel ----------------
__device__ void prep_region(int b, const float* __restrict__ W,
                            const float* __restrict__ We,
                            const float* __restrict__ a_s,
                            const float* __restrict__ a_d,
                            const float* __restrict__ a_e,
                            int KD, int C, int wa_blocks, int layer) {
    int lane = threadIdx.x & 31;
    int wrp = threadIdx.x >> 5;
    if (b < wa_blocks) {
        int idx = b * 8 + wrp;
        if (idx < KD * HH) {
            int k = idx / HH, h = idx % HH;
            const float* wrow = W + (size_t)k * HH * C + h * C;
            const float* as = a_s + h * C;
            const float* ad = a_d + h * C;
            float s = 0.f, d = 0.f;
            for (int c = lane; c < C; c += 32) {
                float w = wrow[c];
                s += w * as[c];
                d += w * ad[c];
            }
#pragma unroll
            for (int o = 16; o; o >>= 1) {
                s += __shfl_xor_sync(0xffffffffu, s, o);
                d += __shfl_xor_sync(0xffffffffu, d, o);
            }
            if (lane == 0) {
                g_Was[layer * 1024 + h * KD + k] = s;
                g_Wad[layer * 1024 + h * KD + k] = d;
            }
        }
    } else {
        int idx = (b - wa_blocks) * 8 + wrp;
        if (idx < EDIM * HH) {
            int d = idx / HH, h = idx % HH;
            const float* werow = We + (size_t)d * HH * C + h * C;
            const float* ae = a_e + h * C;
            float s = 0.f;
            for (int c = lane; c < C; c += 32) s += werow[c] * ae[c];
#pragma unroll
            for (int o = 16; o; o >>= 1) s += __shfl_xor_sync(0xffffffffu, s, o);
            if (lane == 0) g_M[layer * EDIM * HH + d * HH + h] = s;
        }
    }
}

__device__ void trans_region(int tile, const float* __restrict__ W, int KD, int CD,
                             __nv_bfloat16* __restrict__ bhi,
                             __nv_bfloat16* __restrict__ blo, float* sbuf /*32*33*/) {
    int KG = HH * KD;
    int ntx = KG / 32;
    int kg0 = (tile % ntx) * 32;
    int n0 = (tile / ntx) * 32;
    int tx = threadIdx.x & 31, ty = threadIdx.x >> 5;   // 256 threads -> (32,8)
#pragma unroll
    for (int i = 0; i < 4; i++) {
        int kg = kg0 + ty * 4 + i;
        int k = kg % KD, h = kg / KD;
        sbuf[(ty * 4 + i) * 33 + tx] = W[(size_t)k * (HH * CD) + h * CD + n0 + tx] * 0.25f;
    }
    __syncthreads();
#pragma unroll
    for (int i = 0; i < 4; i++) {
        int r = ty * 4 + i;                    // n_local
        float v = sbuf[tx * 33 + r];
        __nv_bfloat16 hi = __float2bfloat16(v);
        float rem = v - __bfloat162float(hi);
        size_t o = (size_t)(n0 + r) * KG + kg0 + tx;
        bhi[o] = hi;
        blo[o] = __float2bfloat16(rem);
    }
}

// fused: CSR scatter + all-layer prep + all-layer weight transpose/split
// regions: [0,625) scatter | prep L0 [625,705) | L1 [705,785) | L2 [785,929)
//          trans L0 [929,993) | L1 [993,1121) | L2 [1121,1249)
__global__ void __launch_bounds__(256) k_big(
    const int* __restrict__ dst,
    const float* __restrict__ W0, const float* __restrict__ We0,
    const float* __restrict__ As0, const float* __restrict__ Ad0,
    const float* __restrict__ Ae0,
    const float* __restrict__ W1, const float* __restrict__ We1,
    const float* __restrict__ As1, const float* __restrict__ Ad1,
    const float* __restrict__ Ae1,
    const float* __restrict__ W2, const float* __restrict__ We2,
    const float* __restrict__ As2, const float* __restrict__ Ad2,
    const float* __restrict__ Ae2,
    __nv_bfloat16* __restrict__ bhi, __nv_bfloat16* __restrict__ blo) {
    __shared__ float sbuf[32 * 33];
    int b = blockIdx.x;
    if (b < 625) {
        int e = b * 256 + threadIdx.x;
        if (e < EE) {
            int p = atomicAdd(&g_cursor[dst[e]], 1);
            g_eperm[p] = e;
        }
    } else if (b < 705) {
        prep_region(b - 625, W0, We0, As0, Ad0, Ae0, 128, 128, 64, 0);
    } else if (b < 785) {
        prep_region(b - 705, W1, We1, As1, Ad1, Ae1, 128, 256, 64, 1);
    } else if (b < 929) {
        prep_region(b - 785, W2, We2, As2, Ad2, Ae2, 256, 128, 128, 2);
    } else if (b < 993) {
        trans_region(b - 929, W0, 128, 128, bhi, blo, sbuf);
    } else if (b < 1121) {
        trans_region(b - 993, W1, 128, 256, bhi + 65536, blo + 65536, sbuf);
    } else {
        trans_region(b - 1121, W2, 256, 128, bhi + 196608, blo + 196608, sbuf);
    }
}

// ---------------- per-edge attention logits, all 3 layers in one pass ----------------
__global__ void k_ale_all(const float* __restrict__ eattr) {
    __shared__ float Ms[3 * EDIM * HH];
    for (int i = threadIdx.x; i < 3 * EDIM * HH; i += blockDim.x) Ms[i] = g_M[i];
    __syncthreads();
    int e = blockIdx.x * blockDim.x + threadIdx.x;
    if (e >= EE) return;
    float a[3][HH];
#pragma unroll
    for (int l = 0; l < 3; l++)
#pragma unroll
        for (int h = 0; h < HH; h++) a[l][h] = 0.f;
    const float4* ep = (const float4*)(eattr + (size_t)e * EDIM);
#pragma unroll
    for (int q = 0; q < EDIM / 4; q++) {
        float4 v = ep[q];
        int d = q * 4;
#pragma unroll
        for (int l = 0; l < 3; l++) {
            const float* M = Ms + l * EDIM * HH;
#pragma unroll
            for (int h = 0; h < HH; h++) {
                a[l][h] += v.x * M[(d + 0) * HH + h] + v.y * M[(d + 1) * HH + h]
                         + v.z * M[(d + 2) * HH + h] + v.w * M[(d + 3) * HH + h];
            }
        }
    }
#pragma unroll
    for (int l = 0; l < 3; l++)
        *(float4*)(g_ale + (size_t)l * EE * HH + (size_t)e * HH)
            = make_float4(a[l][0], a[l][1], a[l][2], a[l][3]);
}

// ---------------- per-node attention coefficients: al = x @ Wa ----------------
__global__ void k_al(const float* __restrict__ x, const float* __restrict__ Was_g,
                     const float* __restrict__ Wad_g, int KD) {
    __shared__ float Was[HH * 256];
    __shared__ float Wad[HH * 256];
    int tid = threadIdx.x;
    for (int i = tid; i < HH * KD; i += 256) { Was[i] = Was_g[i]; Wad[i] = Wad_g[i]; }
    __syncthreads();
    int lane = tid & 31;
    int n = blockIdx.x * 8 + (tid >> 5);
    if (n >= NN) return;
    float s[HH] = {0, 0, 0, 0}, d[HH] = {0, 0, 0, 0};
    const float* xrow = x + (size_t)n * KD;
    for (int k = lane; k < KD; k += 32) {
        float xv = xrow[k];
#pragma unroll
        for (int h = 0; h < HH; h++) {
            s[h] += xv * Was[h * KD + k];
            d[h] += xv * Wad[h * KD + k];
        }
    }
#pragma unroll
    for (int h = 0; h < HH; h++)
#pragma unroll
        for (int o = 16; o; o >>= 1) {
            s[h] += __shfl_xor_sync(0xffffffffu, s[h], o);
            d[h] += __shfl_xor_sync(0xffffffffu, d[h], o);
        }
    if (lane == 0) {
        *(float4*)(g_alsrc + n * HH) = make_float4(s[0], s[1], s[2], s[3]);
        *(float4*)(g_aldst + n * HH) = make_float4(d[0], d[1], d[2], d[3]);
    }
}

// ---------------- fused segment-softmax + x-space aggregation -> bf16 splits ----------------
__device__ __forceinline__ float lrelu(float v) { return v >= 0.f ? v : 0.2f * v; }

template <int KD>
__global__ void __launch_bounds__(128) k_fsa(const int* __restrict__ src,
                                             const float* __restrict__ x,
                                             const float* __restrict__ ale,
                                             __nv_bfloat16* __restrict__ yhi,
                                             __nv_bfloat16* __restrict__ ylo) {
    constexpr int CAP = 512;
    constexpr int R = KD / 128;
    constexpr int KG = HH * KD;
    __shared__ int   ss[CAP];
    __shared__ float sw[HH][CAP];
    __shared__ float red[32];
    __shared__ float bc[12];

    int n = blockIdx.x;
    int tid = threadIdx.x, lane = tid & 31, wrp = tid >> 5;
    int st = g_rowptr[n], en = g_rowptr[n + 1];
    int deg = en - st;
    bool cached = (deg <= CAP);

    float4 ad4 = *(const float4*)(g_aldst + n * HH);
    float4 an4 = *(const float4*)(g_alsrc + n * HH);
    float adst[HH] = {ad4.x, ad4.y, ad4.z, ad4.w};
    float asrcn[HH] = {an4.x, an4.y, an4.z, an4.w};

    float lmx[HH] = {-1e30f, -1e30f, -1e30f, -1e30f};
    float lsa[HH] = {0, 0, 0, 0};
    for (int j = tid; j < deg; j += 128) {
        int e = g_eperm[st + j];
        int s = src[e];
        float4 al4 = *(const float4*)(ale + (size_t)e * HH);
        float4 as4 = *(const float4*)(g_alsrc + (size_t)s * HH);
        float l0 = lrelu(as4.x + adst[0] + al4.x);
        float l1 = lrelu(as4.y + adst[1] + al4.y);
        float l2 = lrelu(as4.z + adst[2] + al4.z);
        float l3 = lrelu(as4.w + adst[3] + al4.w);
        lsa[0] += al4.x; lsa[1] += al4.y; lsa[2] += al4.z; lsa[3] += al4.w;
        lmx[0] = fmaxf(lmx[0], l0); lmx[1] = fmaxf(lmx[1], l1);
        lmx[2] = fmaxf(lmx[2], l2); lmx[3] = fmaxf(lmx[3], l3);
        if (cached) {
            ss[j] = s;
            sw[0][j] = l0; sw[1][j] = l1; sw[2][j] = l2; sw[3][j] = l3;
        }
    }
#pragma unroll
    for (int h = 0; h < HH; h++)
#pragma unroll
        for (int o = 16; o; o >>= 1) {
            lmx[h] = fmaxf(lmx[h], __shfl_xor_sync(0xffffffffu, lmx[h], o));
            lsa[h] += __shfl_xor_sync(0xffffffffu, lsa[h], o);
        }
    if (lane == 0) {
#pragma unroll
        for (int h = 0; h < HH; h++) { red[wrp * 8 + h] = lmx[h]; red[wrp * 8 + 4 + h] = lsa[h]; }
    }
    __syncthreads();
    if (tid == 0) {
        float inv = 1.f / (float)(deg > 0 ? deg : 1);
#pragma unroll
        for (int h = 0; h < HH; h++) {
            float m = fmaxf(fmaxf(red[h], red[8 + h]), fmaxf(red[16 + h], red[24 + h]));
            float sa = red[4 + h] + red[12 + h] + red[20 + h] + red[28 + h];
            float llog = lrelu(asrcn[h] + adst[h] + sa * inv);
            m = fmaxf(m, llog);
            bc[h] = m;
            bc[4 + h] = expf(llog - m);
        }
    }
    __syncthreads();
    float mx[HH] = {bc[0], bc[1], bc[2], bc[3]};

    float lse[HH] = {0, 0, 0, 0};
    for (int j = tid; j < deg; j += 128) {
        float l[HH];
        int e = -1;
        if (cached) {
#pragma unroll
            for (int h = 0; h < HH; h++) l[h] = sw[h][j];
        } else {
            e = g_eperm[st + j];
            int s = src[e];
            float4 al4 = *(const float4*)(ale + (size_t)e * HH);
            float4 as4 = *(const float4*)(g_alsrc + (size_t)s * HH);
            l[0] = lrelu(as4.x + adst[0] + al4.x);
            l[1] = lrelu(as4.y + adst[1] + al4.y);
            l[2] = lrelu(as4.z + adst[2] + al4.z);
            l[3] = lrelu(as4.w + adst[3] + al4.w);
        }
        float w[HH];
#pragma unroll
        for (int h = 0; h < HH; h++) { w[h] = expf(l[h] - mx[h]); lse[h] += w[h]; }
        if (cached) {
#pragma unroll
            for (int h = 0; h < HH; h++) sw[h][j] = w[h];
        } else {
            *(float4*)(g_expw + (size_t)e * HH) = make_float4(w[0], w[1], w[2], w[3]);
        }
    }
#pragma unroll
    for (int h = 0; h < HH; h++)
#pragma unroll
        for (int o = 16; o; o >>= 1) lse[h] += __shfl_xor_sync(0xffffffffu, lse[h], o);
    if (lane == 0) {
#pragma unroll
        for (int h = 0; h < HH; h++) red[wrp * 8 + h] = lse[h];
    }
    __syncthreads();
    if (tid == 0) {
#pragma unroll
        for (int h = 0; h < HH; h++) {
            float s = red[h] + red[8 + h] + red[16 + h] + red[24 + h];
            bc[8 + h] = 1.f / (s + bc[4 + h] + 1e-16f);
        }
    }
    __syncthreads();

    float acc[R][HH];
#pragma unroll
    for (int r = 0; r < R; r++)
#pragma unroll
        for (int h = 0; h < HH; h++) acc[r][h] = 0.f;

    if (cached) {
        int j = 0;
        // 4x unrolled: 4 independent gather rows in flight (MLP=4)
        for (; j + 4 <= deg; j += 4) {
            int s0 = ss[j + 0], s1 = ss[j + 1], s2 = ss[j + 2], s3 = ss[j + 3];
            float w00 = sw[0][j + 0], w10 = sw[1][j + 0], w20 = sw[2][j + 0], w30 = sw[3][j + 0];
            float w01 = sw[0][j + 1], w11 = sw[1][j + 1], w21 = sw[2][j + 1], w31 = sw[3][j + 1];
            float w02 = sw[0][j + 2], w12 = sw[1][j + 2], w22 = sw[2][j + 2], w32 = sw[3][j + 2];
            float w03 = sw[0][j + 3], w13 = sw[1][j + 3], w23 = sw[2][j + 3], w33 = sw[3][j + 3];
            const float* x0 = x + (size_t)s0 * KD;
            const float* x1 = x + (size_t)s1 * KD;
            const float* x2 = x + (size_t)s2 * KD;
            const float* x3 = x + (size_t)s3 * KD;
            float xv0[R], xv1[R], xv2[R], xv3[R];
#pragma unroll
            for (int r = 0; r < R; r++) {
                xv0[r] = x0[tid + r * 128];
                xv1[r] = x1[tid + r * 128];
                xv2[r] = x2[tid + r * 128];
                xv3[r] = x3[tid + r * 128];
            }
#pragma unroll
            for (int r = 0; r < R; r++) {
                acc[r][0] += w00 * xv0[r] + w01 * xv1[r] + w02 * xv2[r] + w03 * xv3[r];
                acc[r][1] += w10 * xv0[r] + w11 * xv1[r] + w12 * xv2[r] + w13 * xv3[r];
                acc[r][2] += w20 * xv0[r] + w21 * xv1[r] + w22 * xv2[r] + w23 * xv3[r];
                acc[r][3] += w30 * xv0[r] + w31 * xv1[r] + w32 * xv2[r] + w33 * xv3[r];
            }
        }
        for (; j < deg; j++) {
            int s = ss[j];
            float w0 = sw[0][j], w1 = sw[1][j], w2 = sw[2][j], w3 = sw[3][j];
            const float* xrow = x + (size_t)s * KD;
#pragma unroll
            for (int r = 0; r < R; r++) {
                float xv = xrow[tid + r * 128];
                acc[r][0] += w0 * xv; acc[r][1] += w1 * xv;
                acc[r][2] += w2 * xv; acc[r][3] += w3 * xv;
            }
        }
    } else {
        for (int j = 0; j < deg; j++) {
            int e = g_eperm[st + j];
            int s = src[e];
            float4 w4 = *(const float4*)(g_expw + (size_t)e * HH);
            const float* xrow = x + (size_t)s * KD;
#pragma unroll
            for (int r = 0; r < R; r++) {
                float xv = xrow[tid + r * 128];
                acc[r][0] += w4.x * xv; acc[r][1] += w4.y * xv;
                acc[r][2] += w4.z * xv; acc[r][3] += w4.w * xv;
            }
        }
    }
    // self loop
    {
        const float* xrow = x + (size_t)n * KD;
#pragma unroll
        for (int r = 0; r < R; r++) {
            float xv = xrow[tid + r * 128];
            acc[r][0] += bc[4] * xv; acc[r][1] += bc[5] * xv;
            acc[r][2] += bc[6] * xv; acc[r][3] += bc[7] * xv;
        }
    }
#pragma unroll
    for (int r = 0; r < R; r++)
#pragma unroll
        for (int h = 0; h < HH; h++) {
            float v = acc[r][h] * bc[8 + h];
            __nv_bfloat16 hi = __float2bfloat16(v);
            float rem = v - __bfloat162float(hi);
            size_t o = (size_t)n * KG + h * KD + r * 128 + tid;
            yhi[o] = hi;
            ylo[o] = __float2bfloat16(rem);
        }
}

// ---------------- warp-MMA bf16 split GEMM: hout = ELU(y @ B^T + bias) ----------------
template <int KG, int CD>
__global__ void __launch_bounds__(256) k_hgemm(const __nv_bfloat16* __restrict__ yhi,
                                               const __nv_bfloat16* __restrict__ ylo,
                                               const __nv_bfloat16* __restrict__ bhi,
                                               const __nv_bfloat16* __restrict__ blo,
                                               const float* __restrict__ bias,
                                               float* __restrict__ hout) {
    constexpr int NC = KG / 32;
    constexpr int A_HI = 0;
    constexpr int A_LO = 5120;      // 64*80
    constexpr int B_HI = 10240;
    constexpr int B_LO = 20480;     // B_HI + 128*80
    constexpr int STAGE = 30720;
    extern __shared__ char smem[];

    int tid = threadIdx.x;
    int lane = tid & 31, wid = tid >> 5;
    int warp_m = wid >> 2, warp_n = wid & 3;
    int m0 = blockIdx.x * 64;
    int n0 = blockIdx.y * 128;
    uint32_t sbase0 = smem_u32(smem);

    float acc[2][4][4];
#pragma unroll
    for (int i = 0; i < 2; i++)
#pragma unroll
        for (int j = 0; j < 4; j++)
#pragma unroll
            for (int k = 0; k < 4; k++) acc[i][j][k] = 0.f;

    auto load_stage = [&](int kc, int buf) {
        uint32_t sb = sbase0 + buf * STAGE;
        int kg0 = kc * 32;
#pragma unroll
        for (int i = 0; i < 2; i++) {
            int idx = i * 256 + tid;
            int half = idx >> 8;
            int rem = idx & 255;
            int r = rem >> 2, ch = rem & 3;
            int row = m0 + r;
            if (row >= NN) row = NN - 1;
            const __nv_bfloat16* gp = (half ? ylo : yhi) + (size_t)row * KG + kg0 + ch * 8;
            cp_async16(sb + (half ? A_LO : A_HI) + r * 80 + ch * 16, gp);
        }
#pragma unroll
        for (int i = 0; i < 4; i++) {
            int idx = i * 256 + tid;
            int half = idx >> 9;
            int rem = idx & 511;
            int r = rem >> 2, ch = rem & 3;
            const __nv_bfloat16* gp = (half ? blo : bhi) + (size_t)(n0 + r) * KG + kg0 + ch * 8;
            cp_async16(sb + (half ? B_LO : B_HI) + r * 80 + ch * 16, gp);
        }
        cp_commit();
    };

    load_stage(0, 0);

    for (int kc = 0; kc < NC; kc++) {
        int buf = kc & 1;
        if (kc + 1 < NC) { load_stage(kc + 1, buf ^ 1); cp_wait<1>(); }
        else             { cp_wait<0>(); }
        __syncthreads();

        uint32_t sb = sbase0 + buf * STAGE;
#pragma unroll
        for (int k16 = 0; k16 < 2; k16++) {
            uint32_t ah[2][4], al_[2][4];
#pragma unroll
            for (int ma = 0; ma < 2; ma++) {
                int row = warp_m * 32 + ma * 16 + (lane & 7) + ((lane >> 3) & 1) * 8;
                int chunk = lane >> 4;
                uint32_t addr = sb + A_HI + row * 80 + k16 * 32 + chunk * 16;
                ldsm_x4(ah[ma], addr);
                ldsm_x4(al_[ma], addr + (A_LO - A_HI));
            }
            uint32_t bh[2][4], bl[2][4];
#pragma unroll
            for (int g = 0; g < 2; g++) {
                int row = warp_n * 32 + g * 16 + (lane & 7) + ((lane >> 4) & 1) * 8;
                int chunk = (lane >> 3) & 1;
                uint32_t addr = sb + B_HI + row * 80 + k16 * 32 + chunk * 16;
                ldsm_x4(bh[g], addr);
                ldsm_x4(bl[g], addr + (B_LO - B_HI));
            }
#pragma unroll
            for (int ma = 0; ma < 2; ma++)
#pragma unroll
                for (int na = 0; na < 4; na++) {
                    int g = na >> 1, s = (na & 1) * 2;
                    mma_bf16(acc[ma][na], ah[ma], bh[g][s], bh[g][s + 1]);
                    mma_bf16(acc[ma][na], ah[ma], bl[g][s], bl[g][s + 1]);
                    mma_bf16(acc[ma][na], al_[ma], bh[g][s], bh[g][s + 1]);
                }
        }
        __syncthreads();
    }

#pragma unroll
    for (int ma = 0; ma < 2; ma++) {
        int row = m0 + warp_m * 32 + ma * 16 + (lane >> 2);
#pragma unroll
        for (int na = 0; na < 4; na++) {
            int col = n0 + warp_n * 32 + na * 8 + (lane & 3) * 2;
            float b0 = bias[col], b1 = bias[col + 1];
            if (row < NN) {
                float v0 = acc[ma][na][0] + b0;
                float v1 = acc[ma][na][1] + b1;
                float2 o;
                o.x = v0 > 0.f ? v0 : expm1f(v0);
                o.y = v1 > 0.f ? v1 : expm1f(v1);
                *(float2*)(hout + (size_t)row * CD + col) = o;
            }
            if (row + 8 < NN) {
                float v2 = acc[ma][na][2] + b0;
                float v3 = acc[ma][na][3] + b1;
                float2 o;
                o.x = v2 > 0.f ? v2 : expm1f(v2);
                o.y = v3 > 0.f ? v3 : expm1f(v3);
                *(float2*)(hout + (size_t)(row + 8) * CD + col) = o;
            }
        }
    }
}

// ---------------- graph mean pooling (batch sorted -> contiguous ranges) ----------------
__global__ void k_pool2(const int* __restrict__ batch, const float* __restrict__ h,
                        float* __restrict__ out) {
    int g = blockIdx.x;
    int t = threadIdx.x;   // 128
    // binary search: lo = first n with batch[n] >= g, hi = first with >= g+1
    int lo = 0, hiB = NN;
    while (lo < hiB) { int m = (lo + hiB) >> 1; if (batch[m] < g) lo = m + 1; else hiB = m; }
    int lo2 = lo, hi2 = NN;
    while (lo2 < hi2) { int m = (lo2 + hi2) >> 1; if (batch[m] < g + 1) lo2 = m + 1; else hi2 = m; }
    int cnt = lo2 - lo;
    float acc = 0.f;
    int n = lo;
    for (; n + 4 <= lo2; n += 4) {
        float a0 = h[(size_t)(n + 0) * 128 + t];
        float a1 = h[(size_t)(n + 1) * 128 + t];
        float a2 = h[(size_t)(n + 2) * 128 + t];
        float a3 = h[(size_t)(n + 3) * 128 + t];
        acc += (a0 + a1) + (a2 + a3);
    }
    for (; n < lo2; n++) acc += h[(size_t)n * 128 + t];
    out[(size_t)g * 128 + t] = acc / (float)(cnt > 0 ? cnt : 1);
}

// ---------------- launch ----------------
extern "C" void kernel_launch(void* const* d_in, const int* in_sizes, int n_in,
                              void* d_out, int out_size) {
    const float* x     = (const float*)d_in[0];
    const int*   ei    = (const int*)d_in[1];
    const float* eattr = (const float*)d_in[2];
    const int*   batch = (const int*)d_in[3];
    const int* src = ei;
    const int* dst = ei + EE;

    const float* W[3]  = {(const float*)d_in[4],  (const float*)d_in[10], (const float*)d_in[16]};
    const float* We[3] = {(const float*)d_in[5],  (const float*)d_in[11], (const float*)d_in[17]};
    const float* As[3] = {(const float*)d_in[6],  (const float*)d_in[12], (const float*)d_in[18]};
    const float* Ad[3] = {(const float*)d_in[7],  (const float*)d_in[13], (const float*)d_in[19]};
    const float* Ae[3] = {(const float*)d_in[8],  (const float*)d_in[14], (const float*)d_in[20]};
    const float* Bb[3] = {(const float*)d_in[9],  (const float*)d_in[15], (const float*)d_in[21]};
    (void)n_in; (void)in_sizes; (void)out_size;

    float* out = (float*)d_out;

    void *p_deg, *p_yhi, *p_ylo, *p_hA, *p_hB, *p_bhi, *p_blo, *p_ale, *p_was, *p_wad;
    cudaGetSymbolAddress(&p_deg, g_deg);
    cudaGetSymbolAddress(&p_yhi, g_yhi);
    cudaGetSymbolAddress(&p_ylo, g_ylo);
    cudaGetSymbolAddress(&p_hA, g_hA);
    cudaGetSymbolAddress(&p_hB, g_hB);
    cudaGetSymbolAddress(&p_bhi, g_bhi);
    cudaGetSymbolAddress(&p_blo, g_blo);
    cudaGetSymbolAddress(&p_ale, g_ale);
    cudaGetSymbolAddress(&p_was, g_Was);
    cudaGetSymbolAddress(&p_wad, g_Wad);
    __nv_bfloat16* yhi = (__nv_bfloat16*)p_yhi;
    __nv_bfloat16* ylo = (__nv_bfloat16*)p_ylo;
    float* hA = (float*)p_hA;
    float* hB = (float*)p_hB;
    __nv_bfloat16* bhi = (__nv_bfloat16*)p_bhi;
    __nv_bfloat16* blo = (__nv_bfloat16*)p_blo;
    float* ale = (float*)p_ale;
    float* wasp = (float*)p_was;
    float* wadp = (float*)p_wad;

    const int SMEM_BYTES = 61440;
    cudaFuncSetAttribute((const void*)k_hgemm<512, 128>,
                         cudaFuncAttributeMaxDynamicSharedMemorySize, SMEM_BYTES);
    cudaFuncSetAttribute((const void*)k_hgemm<512, 256>,
                         cudaFuncAttributeMaxDynamicSharedMemorySize, SMEM_BYTES);
    cudaFuncSetAttribute((const void*)k_hgemm<1024, 128>,
                         cudaFuncAttributeMaxDynamicSharedMemorySize, SMEM_BYTES);

    cudaMemsetAsync(p_deg, 0, NN * sizeof(int));

    // launch #0..#2: CSR build + fused setup (scatter + prep + trans)
    k_deg<<<(EE + 255) / 256, 256>>>(dst);
    k_scan<<<1, 1024>>>();
    k_big<<<1249, 256>>>(dst,
                         W[0], We[0], As[0], Ad[0], Ae[0],
                         W[1], We[1], As[1], Ad[1], Ae[1],
                         W[2], We[2], As[2], Ad[2], Ae[2],
                         bhi, blo);
    // #3
    k_ale_all<<<(EE + 127) / 128, 128>>>(eattr);

    const int Kdim[3] = {128, 128, 256};
    const size_t boff[3] = {0, 65536, 196608};
    const float* lin[3]  = {x, hA, hB};
    float*       lout[3] = {hA, hB, hA};
    const int MB = (NN + 63) / 64;   // 157

    for (int l = 0; l < 3; l++) {
        int Kd = Kdim[l];
        // #4 (l=0): k_al ; #5 (l=0): k_fsa  <- ncu -s 5 captures k_fsa layer 0
        k_al<<<(NN + 7) / 8, 256>>>(lin[l], wasp + l * 1024, wadp + l * 1024, Kd);
        if (Kd == 128)
            k_fsa<128><<<NN, 128>>>(src, lin[l], ale + (size_t)l * EE * HH, yhi, ylo);
        else
            k_fsa<256><<<NN, 128>>>(src, lin[l], ale + (size_t)l * EE * HH, yhi, ylo);
        if (l == 0)
            k_hgemm<512, 128><<<dim3(MB, 1), 256, SMEM_BYTES>>>(
                yhi, ylo, bhi + boff[0], blo + boff[0], Bb[0], lout[0]);
        else if (l == 1)
            k_hgemm<512, 256><<<dim3(MB, 2), 256, SMEM_BYTES>>>(
                yhi, ylo, bhi + boff[1], blo + boff[1], Bb[1], lout[1]);
        else
            k_hgemm<1024, 128><<<dim3(MB, 1), 256, SMEM_BYTES>>>(
                yhi, ylo, bhi + boff[2], blo + boff[2], Bb[2], lout[2]);
    }

    k_pool2<<<GG, 128>>>(batch, hA, out);
}

// round 8
// speedup vs baseline: 2.0629x; 1.0166x over previous
#include <cuda_runtime.h>
#include <cuda_bf16.h>
#include <math.h>
#include <stdint.h>

#define NN 10000
#define EE 160000
#define GG 64
#define HH 4
#define EDIM 32

// ---------------- static scratch ----------------
__device__ int   g_deg[NN];
__device__ int   g_rowptr[NN + 1];
__device__ int   g_cursor[NN];
__device__ int   g_eperm[EE];
__device__ __nv_bfloat16 g_yhi[(size_t)NN * 1024];
__device__ __nv_bfloat16 g_ylo[(size_t)NN * 1024];
__device__ float g_hA[(size_t)NN * 256];
__device__ float g_hB[(size_t)NN * 256];
__device__ float g_alsrc[NN * HH];
__device__ float g_aldst[NN * HH];
__device__ float g_ale[(size_t)3 * EE * HH];
__device__ float g_expw[(size_t)EE * HH];     // fallback (deg > 512)
__device__ float g_M[3 * HH * EDIM];          // [l][h][d]
__device__ float g_Was[3 * 1024];             // per-layer [l][h*KD+k]
__device__ float g_Wad[3 * 1024];
__device__ __nv_bfloat16 g_bhi[327680];
__device__ __nv_bfloat16 g_blo[327680];

// ---------------- generic PTX helpers (compute_103-safe) ----------------
__device__ __forceinline__ uint32_t smem_u32(const void* p) {
    uint32_t a;
    asm("{ .reg .u64 t; cvta.to.shared.u64 t, %1; cvt.u32.u64 %0, t; }"
        : "=r"(a) : "l"(p));
    return a;
}
__device__ __forceinline__ void cp_async16(uint32_t saddr, const void* gptr) {
    asm volatile("cp.async.ca.shared.global [%0], [%1], 16;"
                 :: "r"(saddr), "l"(gptr) : "memory");
}
__device__ __forceinline__ void cp_commit() {
    asm volatile("cp.async.commit_group;" ::: "memory");
}
template <int N>
__device__ __forceinline__ void cp_wait() {
    asm volatile("cp.async.wait_group %0;" :: "n"(N) : "memory");
}
__device__ __forceinline__ void ldsm_x4(uint32_t* r, uint32_t addr) {
    asm volatile("ldmatrix.sync.aligned.m8n8.x4.shared.b16 {%0,%1,%2,%3}, [%4];"
                 : "=r"(r[0]), "=r"(r[1]), "=r"(r[2]), "=r"(r[3]) : "r"(addr));
}
__device__ __forceinline__ void mma_bf16(float* d, const uint32_t* a,
                                         uint32_t b0, uint32_t b1) {
    asm volatile(
        "mma.sync.aligned.m16n8k16.row.col.f32.bf16.bf16.f32 "
        "{%0,%1,%2,%3}, {%4,%5,%6,%7}, {%8,%9}, {%0,%1,%2,%3};"
        : "+f"(d[0]), "+f"(d[1]), "+f"(d[2]), "+f"(d[3])
        : "r"(a[0]), "r"(a[1]), "r"(a[2]), "r"(a[3]), "r"(b0), "r"(b1));
}

// ---------------- CSR build ----------------
__global__ void k_deg(const int* __restrict__ dst) {
    int e = blockIdx.x * blockDim.x + threadIdx.x;
    if (e < EE) atomicAdd(&g_deg[dst[e]], 1);
}

// single block, 1024 threads, 10 elements/thread (NN = 10000 = 1000*10)
__global__ void __launch_bounds__(1024) k_scan() {
    __shared__ int wsum[32];
    int t = threadIdx.x;
    int lane = t & 31, w = t >> 5;
    int v[10];
    int s = 0;
    int base = t * 10;
    if (t < 1000) {
#pragma unroll
        for (int i = 0; i < 10; i++) { v[i] = g_deg[base + i]; s += v[i]; }
    }
    // inclusive warp scan of per-thread sums
    int ps = s;
#pragma unroll
    for (int o = 1; o < 32; o <<= 1) {
        int u = __shfl_up_sync(0xffffffffu, ps, o);
        if (lane >= o) ps += u;
    }
    if (lane == 31) wsum[w] = ps;
    __syncthreads();
    if (w == 0) {
        int xv = wsum[lane];
#pragma unroll
        for (int o = 1; o < 32; o <<= 1) {
            int u = __shfl_up_sync(0xffffffffu, xv, o);
            if (lane >= o) xv += u;
        }
        wsum[lane] = xv;
    }
    __syncthreads();
    int excl = ps - s + (w > 0 ? wsum[w - 1] : 0);
    if (t == 0) g_rowptr[0] = 0;
    if (t < 1000) {
        int run = excl;
#pragma unroll
        for (int i = 0; i < 10; i++) {
            g_cursor[base + i] = run;
            run += v[i];
            g_rowptr[base + i + 1] = run;
        }
    }
}

// ---------------- region helpers for the fused setup kernel ----------------
__device__ void prep_region(int b, const float* __restrict__ W,
                            const float* __restrict__ We,
                            const float* __restrict__ a_s,
                            const float* __restrict__ a_d,
                            const float* __restrict__ a_e,
                            int KD, int C, int wa_blocks, int layer) {
    int lane = threadIdx.x & 31;
    int wrp = threadIdx.x >> 5;
    if (b < wa_blocks) {
        int idx = b * 8 + wrp;
        if (idx < KD * HH) {
            int k = idx / HH, h = idx % HH;
            const float* wrow = W + (size_t)k * HH * C + h * C;
            const float* as = a_s + h * C;
            const float* ad = a_d + h * C;
            float s = 0.f, d = 0.f;
            for (int c = lane; c < C; c += 32) {
                float w = wrow[c];
                s += w * as[c];
                d += w * ad[c];
            }
#pragma unroll
            for (int o = 16; o; o >>= 1) {
                s += __shfl_xor_sync(0xffffffffu, s, o);
                d += __shfl_xor_sync(0xffffffffu, d, o);
            }
            if (lane == 0) {
                g_Was[layer * 1024 + h * KD + k] = s;
                g_Wad[layer * 1024 + h * KD + k] = d;
            }
        }
    } else {
        int idx = (b - wa_blocks) * 8 + wrp;
        if (idx < EDIM * HH) {
            int d = idx / HH, h = idx % HH;
            const float* werow = We + (size_t)d * HH * C + h * C;
            const float* ae = a_e + h * C;
            float s = 0.f;
            for (int c = lane; c < C; c += 32) s += werow[c] * ae[c];
#pragma unroll
            for (int o = 16; o; o >>= 1) s += __shfl_xor_sync(0xffffffffu, s, o);
            // layout [l][h][d]
            if (lane == 0) g_M[layer * (HH * EDIM) + h * EDIM + d] = s;
        }
    }
}

__device__ void trans_region(int tile, const float* __restrict__ W, int KD, int CD,
                             __nv_bfloat16* __restrict__ bhi,
                             __nv_bfloat16* __restrict__ blo, float* sbuf /*32*33*/) {
    int KG = HH * KD;
    int ntx = KG / 32;
    int kg0 = (tile % ntx) * 32;
    int n0 = (tile / ntx) * 32;
    int tx = threadIdx.x & 31, ty = threadIdx.x >> 5;   // 256 threads -> (32,8)
#pragma unroll
    for (int i = 0; i < 4; i++) {
        int kg = kg0 + ty * 4 + i;
        int k = kg % KD, h = kg / KD;
        sbuf[(ty * 4 + i) * 33 + tx] = W[(size_t)k * (HH * CD) + h * CD + n0 + tx] * 0.25f;
    }
    __syncthreads();
#pragma unroll
    for (int i = 0; i < 4; i++) {
        int r = ty * 4 + i;                    // n_local
        float v = sbuf[tx * 33 + r];
        __nv_bfloat16 hi = __float2bfloat16(v);
        float rem = v - __bfloat162float(hi);
        size_t o = (size_t)(n0 + r) * KG + kg0 + tx;
        bhi[o] = hi;
        blo[o] = __float2bfloat16(rem);
    }
}

// fused: CSR scatter + all-layer prep + all-layer weight transpose/split
__global__ void __launch_bounds__(256) k_big(
    const int* __restrict__ dst,
    const float* __restrict__ W0, const float* __restrict__ We0,
    const float* __restrict__ As0, const float* __restrict__ Ad0,
    const float* __restrict__ Ae0,
    const float* __restrict__ W1, const float* __restrict__ We1,
    const float* __restrict__ As1, const float* __restrict__ Ad1,
    const float* __restrict__ Ae1,
    const float* __restrict__ W2, const float* __restrict__ We2,
    const float* __restrict__ As2, const float* __restrict__ Ad2,
    const float* __restrict__ Ae2,
    __nv_bfloat16* __restrict__ bhi, __nv_bfloat16* __restrict__ blo) {
    __shared__ float sbuf[32 * 33];
    int b = blockIdx.x;
    if (b < 625) {
        int e = b * 256 + threadIdx.x;
        if (e < EE) {
            int p = atomicAdd(&g_cursor[dst[e]], 1);
            g_eperm[p] = e;
        }
    } else if (b < 705) {
        prep_region(b - 625, W0, We0, As0, Ad0, Ae0, 128, 128, 64, 0);
    } else if (b < 785) {
        prep_region(b - 705, W1, We1, As1, Ad1, Ae1, 128, 256, 64, 1);
    } else if (b < 929) {
        prep_region(b - 785, W2, We2, As2, Ad2, Ae2, 256, 128, 128, 2);
    } else if (b < 993) {
        trans_region(b - 929, W0, 128, 128, bhi, blo, sbuf);
    } else if (b < 1121) {
        trans_region(b - 993, W1, 128, 256, bhi + 65536, blo + 65536, sbuf);
    } else {
        trans_region(b - 1121, W2, 256, 128, bhi + 196608, blo + 196608, sbuf);
    }
}

// ---------------- per-edge attention logits, all 3 layers, 2 edges/thread ----------------
__global__ void __launch_bounds__(128) k_ale_all(const float* __restrict__ eattr) {
    __shared__ float4 Ms4[12 * 8];   // [l*4+h][q] — float4 over d
    int tid = threadIdx.x;
    if (tid < 96) {
        int lh = tid >> 3, q = tid & 7;
        Ms4[lh * 8 + q] = *(const float4*)(g_M + lh * EDIM + q * 4);
    }
    __syncthreads();
    int gid = blockIdx.x * blockDim.x + tid;
    if (gid >= EE / 2) return;
    int e0 = gid, e1 = gid + EE / 2;
    const float4* p0 = (const float4*)(eattr + (size_t)e0 * EDIM);
    const float4* p1 = (const float4*)(eattr + (size_t)e1 * EDIM);
    float a0[12], a1[12];
#pragma unroll
    for (int i = 0; i < 12; i++) { a0[i] = 0.f; a1[i] = 0.f; }
#pragma unroll
    for (int q = 0; q < 8; q++) {
        float4 v0 = p0[q], v1 = p1[q];
#pragma unroll
        for (int lh = 0; lh < 12; lh++) {
            float4 m = Ms4[lh * 8 + q];
            a0[lh] += v0.x * m.x + v0.y * m.y + v0.z * m.z + v0.w * m.w;
            a1[lh] += v1.x * m.x + v1.y * m.y + v1.z * m.z + v1.w * m.w;
        }
    }
#pragma unroll
    for (int l = 0; l < 3; l++) {
        *(float4*)(g_ale + (size_t)l * EE * HH + (size_t)e0 * HH)
            = make_float4(a0[l * 4 + 0], a0[l * 4 + 1], a0[l * 4 + 2], a0[l * 4 + 3]);
        *(float4*)(g_ale + (size_t)l * EE * HH + (size_t)e1 * HH)
            = make_float4(a1[l * 4 + 0], a1[l * 4 + 1], a1[l * 4 + 2], a1[l * 4 + 3]);
    }
}

// ---------------- per-node attention coefficients: al = x @ Wa ----------------
__global__ void k_al(const float* __restrict__ x, const float* __restrict__ Was_g,
                     const float* __restrict__ Wad_g, int KD) {
    __shared__ float Was[HH * 256];
    __shared__ float Wad[HH * 256];
    int tid = threadIdx.x;
    for (int i = tid; i < HH * KD; i += 256) { Was[i] = Was_g[i]; Wad[i] = Wad_g[i]; }
    __syncthreads();
    int lane = tid & 31;
    int n = blockIdx.x * 8 + (tid >> 5);
    if (n >= NN) return;
    float s[HH] = {0, 0, 0, 0}, d[HH] = {0, 0, 0, 0};
    const float* xrow = x + (size_t)n * KD;
    for (int k = lane; k < KD; k += 32) {
        float xv = xrow[k];
#pragma unroll
        for (int h = 0; h < HH; h++) {
            s[h] += xv * Was[h * KD + k];
            d[h] += xv * Wad[h * KD + k];
        }
    }
#pragma unroll
    for (int h = 0; h < HH; h++)
#pragma unroll
        for (int o = 16; o; o >>= 1) {
            s[h] += __shfl_xor_sync(0xffffffffu, s[h], o);
            d[h] += __shfl_xor_sync(0xffffffffu, d[h], o);
        }
    if (lane == 0) {
        *(float4*)(g_alsrc + n * HH) = make_float4(s[0], s[1], s[2], s[3]);
        *(float4*)(g_aldst + n * HH) = make_float4(d[0], d[1], d[2], d[3]);
    }
}

// ---------------- fused segment-softmax + x-space aggregation -> bf16 splits ----------------
__device__ __forceinline__ float lrelu(float v) { return v >= 0.f ? v : 0.2f * v; }

template <int KD>
__global__ void __launch_bounds__(128) k_fsa(const int* __restrict__ src,
                                             const float* __restrict__ x,
                                             const float* __restrict__ ale,
                                             __nv_bfloat16* __restrict__ yhi,
                                             __nv_bfloat16* __restrict__ ylo) {
    constexpr int CAP = 512;
    constexpr int R = KD / 128;
    constexpr int KG = HH * KD;
    __shared__ int   ss[CAP];
    __shared__ float sw[HH][CAP];
    __shared__ float red[32];
    __shared__ float bc[12];

    int n = blockIdx.x;
    int tid = threadIdx.x, lane = tid & 31, wrp = tid >> 5;
    int st = g_rowptr[n], en = g_rowptr[n + 1];
    int deg = en - st;
    bool cached = (deg <= CAP);

    float4 ad4 = *(const float4*)(g_aldst + n * HH);
    float4 an4 = *(const float4*)(g_alsrc + n * HH);
    float adst[HH] = {ad4.x, ad4.y, ad4.z, ad4.w};
    float asrcn[HH] = {an4.x, an4.y, an4.z, an4.w};

    float lmx[HH] = {-1e30f, -1e30f, -1e30f, -1e30f};
    float lsa[HH] = {0, 0, 0, 0};
    for (int j = tid; j < deg; j += 128) {
        int e = g_eperm[st + j];
        int s = src[e];
        float4 al4 = *(const float4*)(ale + (size_t)e * HH);
        float4 as4 = *(const float4*)(g_alsrc + (size_t)s * HH);
        float l0 = lrelu(as4.x + adst[0] + al4.x);
        float l1 = lrelu(as4.y + adst[1] + al4.y);
        float l2 = lrelu(as4.z + adst[2] + al4.z);
        float l3 = lrelu(as4.w + adst[3] + al4.w);
        lsa[0] += al4.x; lsa[1] += al4.y; lsa[2] += al4.z; lsa[3] += al4.w;
        lmx[0] = fmaxf(lmx[0], l0); lmx[1] = fmaxf(lmx[1], l1);
        lmx[2] = fmaxf(lmx[2], l2); lmx[3] = fmaxf(lmx[3], l3);
        if (cached) {
            ss[j] = s;
            sw[0][j] = l0; sw[1][j] = l1; sw[2][j] = l2; sw[3][j] = l3;
        }
    }
#pragma unroll
    for (int h = 0; h < HH; h++)
#pragma unroll
        for (int o = 16; o; o >>= 1) {
            lmx[h] = fmaxf(lmx[h], __shfl_xor_sync(0xffffffffu, lmx[h], o));
            lsa[h] += __shfl_xor_sync(0xffffffffu, lsa[h], o);
        }
    if (lane == 0) {
#pragma unroll
        for (int h = 0; h < HH; h++) { red[wrp * 8 + h] = lmx[h]; red[wrp * 8 + 4 + h] = lsa[h]; }
    }
    __syncthreads();
    if (tid == 0) {
        float inv = 1.f / (float)(deg > 0 ? deg : 1);
#pragma unroll
        for (int h = 0; h < HH; h++) {
            float m = fmaxf(fmaxf(red[h], red[8 + h]), fmaxf(red[16 + h], red[24 + h]));
            float sa = red[4 + h] + red[12 + h] + red[20 + h] + red[28 + h];
            float llog = lrelu(asrcn[h] + adst[h] + sa * inv);
            m = fmaxf(m, llog);
            bc[h] = m;
            bc[4 + h] = expf(llog - m);
        }
    }
    __syncthreads();
    float mx[HH] = {bc[0], bc[1], bc[2], bc[3]};

    float lse[HH] = {0, 0, 0, 0};
    for (int j = tid; j < deg; j += 128) {
        float l[HH];
        int e = -1;
        if (cached) {
#pragma unroll
            for (int h = 0; h < HH; h++) l[h] = sw[h][j];
        } else {
            e = g_eperm[st + j];
            int s = src[e];
            float4 al4 = *(const float4*)(ale + (size_t)e * HH);
            float4 as4 = *(const float4*)(g_alsrc + (size_t)s * HH);
            l[0] = lrelu(as4.x + adst[0] + al4.x);
            l[1] = lrelu(as4.y + adst[1] + al4.y);
            l[2] = lrelu(as4.z + adst[2] + al4.z);
            l[3] = lrelu(as4.w + adst[3] + al4.w);
        }
        float w[HH];
#pragma unroll
        for (int h = 0; h < HH; h++) { w[h] = expf(l[h] - mx[h]); lse[h] += w[h]; }
        if (cached) {
#pragma unroll
            for (int h = 0; h < HH; h++) sw[h][j] = w[h];
        } else {
            *(float4*)(g_expw + (size_t)e * HH) = make_float4(w[0], w[1], w[2], w[3]);
        }
    }
#pragma unroll
    for (int h = 0; h < HH; h++)
#pragma unroll
        for (int o = 16; o; o >>= 1) lse[h] += __shfl_xor_sync(0xffffffffu, lse[h], o);
    if (lane == 0) {
#pragma unroll
        for (int h = 0; h < HH; h++) red[wrp * 8 + h] = lse[h];
    }
    __syncthreads();
    if (tid == 0) {
#pragma unroll
        for (int h = 0; h < HH; h++) {
            float s = red[h] + red[8 + h] + red[16 + h] + red[24 + h];
            bc[8 + h] = 1.f / (s + bc[4 + h] + 1e-16f);
        }
    }
    __syncthreads();

    float acc[R][HH];
#pragma unroll
    for (int r = 0; r < R; r++)
#pragma unroll
        for (int h = 0; h < HH; h++) acc[r][h] = 0.f;

    if (cached) {
        int j = 0;
        for (; j + 4 <= deg; j += 4) {
            int s0 = ss[j + 0], s1 = ss[j + 1], s2 = ss[j + 2], s3 = ss[j + 3];
            float w00 = sw[0][j + 0], w10 = sw[1][j + 0], w20 = sw[2][j + 0], w30 = sw[3][j + 0];
            float w01 = sw[0][j + 1], w11 = sw[1][j + 1], w21 = sw[2][j + 1], w31 = sw[3][j + 1];
            float w02 = sw[0][j + 2], w12 = sw[1][j + 2], w22 = sw[2][j + 2], w32 = sw[3][j + 2];
            float w03 = sw[0][j + 3], w13 = sw[1][j + 3], w23 = sw[2][j + 3], w33 = sw[3][j + 3];
            const float* x0 = x + (size_t)s0 * KD;
            const float* x1 = x + (size_t)s1 * KD;
            const float* x2 = x + (size_t)s2 * KD;
            const float* x3 = x + (size_t)s3 * KD;
            float xv0[R], xv1[R], xv2[R], xv3[R];
#pragma unroll
            for (int r = 0; r < R; r++) {
                xv0[r] = x0[tid + r * 128];
                xv1[r] = x1[tid + r * 128];
                xv2[r] = x2[tid + r * 128];
                xv3[r] = x3[tid + r * 128];
            }
#pragma unroll
            for (int r = 0; r < R; r++) {
                acc[r][0] += w00 * xv0[r] + w01 * xv1[r] + w02 * xv2[r] + w03 * xv3[r];
                acc[r][1] += w10 * xv0[r] + w11 * xv1[r] + w12 * xv2[r] + w13 * xv3[r];
                acc[r][2] += w20 * xv0[r] + w21 * xv1[r] + w22 * xv2[r] + w23 * xv3[r];
                acc[r][3] += w30 * xv0[r] + w31 * xv1[r] + w32 * xv2[r] + w33 * xv3[r];
            }
        }
        for (; j < deg; j++) {
            int s = ss[j];
            float w0 = sw[0][j], w1 = sw[1][j], w2 = sw[2][j], w3 = sw[3][j];
            const float* xrow = x + (size_t)s * KD;
#pragma unroll
            for (int r = 0; r < R; r++) {
                float xv = xrow[tid + r * 128];
                acc[r][0] += w0 * xv; acc[r][1] += w1 * xv;
                acc[r][2] += w2 * xv; acc[r][3] += w3 * xv;
            }
        }
    } else {
        for (int j = 0; j < deg; j++) {
            int e = g_eperm[st + j];
            int s = src[e];
            float4 w4 = *(const float4*)(g_expw + (size_t)e * HH);
            const float* xrow = x + (size_t)s * KD;
#pragma unroll
            for (int r = 0; r < R; r++) {
                float xv = xrow[tid + r * 128];
                acc[r][0] += w4.x * xv; acc[r][1] += w4.y * xv;
                acc[r][2] += w4.z * xv; acc[r][3] += w4.w * xv;
            }
        }
    }
    // self loop
    {
        const float* xrow = x + (size_t)n * KD;
#pragma unroll
        for (int r = 0; r < R; r++) {
            float xv = xrow[tid + r * 128];
            acc[r][0] += bc[4] * xv; acc[r][1] += bc[5] * xv;
            acc[r][2] += bc[6] * xv; acc[r][3] += bc[7] * xv;
        }
    }
#pragma unroll
    for (int r = 0; r < R; r++)
#pragma unroll
        for (int h = 0; h < HH; h++) {
            float v = acc[r][h] * bc[8 + h];
            __nv_bfloat16 hi = __float2bfloat16(v);
            float rem = v - __bfloat162float(hi);
            size_t o = (size_t)n * KG + h * KD + r * 128 + tid;
            yhi[o] = hi;
            ylo[o] = __float2bfloat16(rem);
        }
}

// ---------------- warp-MMA bf16 split GEMM: hout = ELU(y @ B^T + bias) ----------------
template <int KG, int CD>
__global__ void __launch_bounds__(256) k_hgemm(const __nv_bfloat16* __restrict__ yhi,
                                               const __nv_bfloat16* __restrict__ ylo,
                                               const __nv_bfloat16* __restrict__ bhi,
                                               const __nv_bfloat16* __restrict__ blo,
                                               const float* __restrict__ bias,
                                               float* __restrict__ hout) {
    constexpr int NC = KG / 32;
    constexpr int A_HI = 0;
    constexpr int A_LO = 5120;      // 64*80
    constexpr int B_HI = 10240;
    constexpr int B_LO = 20480;     // B_HI + 128*80
    constexpr int STAGE = 30720;
    extern __shared__ char smem[];

    int tid = threadIdx.x;
    int lane = tid & 31, wid = tid >> 5;
    int warp_m = wid >> 2, warp_n = wid & 3;
    int m0 = blockIdx.x * 64;
    int n0 = blockIdx.y * 128;
    uint32_t sbase0 = smem_u32(smem);

    float acc[2][4][4];
#pragma unroll
    for (int i = 0; i < 2; i++)
#pragma unroll
        for (int j = 0; j < 4; j++)
#pragma unroll
            for (int k = 0; k < 4; k++) acc[i][j][k] = 0.f;

    auto load_stage = [&](int kc, int buf) {
        uint32_t sb = sbase0 + buf * STAGE;
        int kg0 = kc * 32;
#pragma unroll
        for (int i = 0; i < 2; i++) {
            int idx = i * 256 + tid;
            int half = idx >> 8;
            int rem = idx & 255;
            int r = rem >> 2, ch = rem & 3;
            int row = m0 + r;
            if (row >= NN) row = NN - 1;
            const __nv_bfloat16* gp = (half ? ylo : yhi) + (size_t)row * KG + kg0 + ch * 8;
            cp_async16(sb + (half ? A_LO : A_HI) + r * 80 + ch * 16, gp);
        }
#pragma unroll
        for (int i = 0; i < 4; i++) {
            int idx = i * 256 + tid;
            int half = idx >> 9;
            int rem = idx & 511;
            int r = rem >> 2, ch = rem & 3;
            const __nv_bfloat16* gp = (half ? blo : bhi) + (size_t)(n0 + r) * KG + kg0 + ch * 8;
            cp_async16(sb + (half ? B_LO : B_HI) + r * 80 + ch * 16, gp);
        }
        cp_commit();
    };

    load_stage(0, 0);

    for (int kc = 0; kc < NC; kc++) {
        int buf = kc & 1;
        if (kc + 1 < NC) { load_stage(kc + 1, buf ^ 1); cp_wait<1>(); }
        else             { cp_wait<0>(); }
        __syncthreads();

        uint32_t sb = sbase0 + buf * STAGE;
#pragma unroll
        for (int k16 = 0; k16 < 2; k16++) {
            uint32_t ah[2][4], al_[2][4];
#pragma unroll
            for (int ma = 0; ma < 2; ma++) {
                int row = warp_m * 32 + ma * 16 + (lane & 7) + ((lane >> 3) & 1) * 8;
                int chunk = lane >> 4;
                uint32_t addr = sb + A_HI + row * 80 + k16 * 32 + chunk * 16;
                ldsm_x4(ah[ma], addr);
                ldsm_x4(al_[ma], addr + (A_LO - A_HI));
            }
            uint32_t bh[2][4], bl[2][4];
#pragma unroll
            for (int g = 0; g < 2; g++) {
                int row = warp_n * 32 + g * 16 + (lane & 7) + ((lane >> 4) & 1) * 8;
                int chunk = (lane >> 3) & 1;
                uint32_t addr = sb + B_HI + row * 80 + k16 * 32 + chunk * 16;
                ldsm_x4(bh[g], addr);
                ldsm_x4(bl[g], addr + (B_LO - B_HI));
            }
#pragma unroll
            for (int ma = 0; ma < 2; ma++)
#pragma unroll
                for (int na = 0; na < 4; na++) {
                    int g = na >> 1, s = (na & 1) * 2;
                    mma_bf16(acc[ma][na], ah[ma], bh[g][s], bh[g][s + 1]);
                    mma_bf16(acc[ma][na], ah[ma], bl[g][s], bl[g][s + 1]);
                    mma_bf16(acc[ma][na], al_[ma], bh[g][s], bh[g][s + 1]);
                }
        }
        __syncthreads();
    }

#pragma unroll
    for (int ma = 0; ma < 2; ma++) {
        int row = m0 + warp_m * 32 + ma * 16 + (lane >> 2);
#pragma unroll
        for (int na = 0; na < 4; na++) {
            int col = n0 + warp_n * 32 + na * 8 + (lane & 3) * 2;
            float b0 = bias[col], b1 = bias[col + 1];
            if (row < NN) {
                float v0 = acc[ma][na][0] + b0;
                float v1 = acc[ma][na][1] + b1;
                float2 o;
                o.x = v0 > 0.f ? v0 : expm1f(v0);
                o.y = v1 > 0.f ? v1 : expm1f(v1);
                *(float2*)(hout + (size_t)row * CD + col) = o;
            }
            if (row + 8 < NN) {
                float v2 = acc[ma][na][2] + b0;
                float v3 = acc[ma][na][3] + b1;
                float2 o;
                o.x = v2 > 0.f ? v2 : expm1f(v2);
                o.y = v3 > 0.f ? v3 : expm1f(v3);
                *(float2*)(hout + (size_t)(row + 8) * CD + col) = o;
            }
        }
    }
}

// ---------------- graph mean pooling (batch sorted -> contiguous ranges) ----------------
__global__ void k_pool2(const int* __restrict__ batch, const float* __restrict__ h,
                        float* __restrict__ out) {
    int g = blockIdx.x;
    int t = threadIdx.x;   // 128
    int lo = 0, hiB = NN;
    while (lo < hiB) { int m = (lo + hiB) >> 1; if (batch[m] < g) lo = m + 1; else hiB = m; }
    int lo2 = lo, hi2 = NN;
    while (lo2 < hi2) { int m = (lo2 + hi2) >> 1; if (batch[m] < g + 1) lo2 = m + 1; else hi2 = m; }
    int cnt = lo2 - lo;
    float acc = 0.f;
    int n = lo;
    for (; n + 4 <= lo2; n += 4) {
        float a0 = h[(size_t)(n + 0) * 128 + t];
        float a1 = h[(size_t)(n + 1) * 128 + t];
        float a2 = h[(size_t)(n + 2) * 128 + t];
        float a3 = h[(size_t)(n + 3) * 128 + t];
        acc += (a0 + a1) + (a2 + a3);
    }
    for (; n < lo2; n++) acc += h[(size_t)n * 128 + t];
    out[(size_t)g * 128 + t] = acc / (float)(cnt > 0 ? cnt : 1);
}

// ---------------- launch ----------------
extern "C" void kernel_launch(void* const* d_in, const int* in_sizes, int n_in,
                              void* d_out, int out_size) {
    const float* x     = (const float*)d_in[0];
    const int*   ei    = (const int*)d_in[1];
    const float* eattr = (const float*)d_in[2];
    const int*   batch = (const int*)d_in[3];
    const int* src = ei;
    const int* dst = ei + EE;

    const float* W[3]  = {(const float*)d_in[4],  (const float*)d_in[10], (const float*)d_in[16]};
    const float* We[3] = {(const float*)d_in[5],  (const float*)d_in[11], (const float*)d_in[17]};
    const float* As[3] = {(const float*)d_in[6],  (const float*)d_in[12], (const float*)d_in[18]};
    const float* Ad[3] = {(const float*)d_in[7],  (const float*)d_in[13], (const float*)d_in[19]};
    const float* Ae[3] = {(const float*)d_in[8],  (const float*)d_in[14], (const float*)d_in[20]};
    const float* Bb[3] = {(const float*)d_in[9],  (const float*)d_in[15], (const float*)d_in[21]};
    (void)n_in; (void)in_sizes; (void)out_size;

    float* out = (float*)d_out;

    void *p_deg, *p_yhi, *p_ylo, *p_hA, *p_hB, *p_bhi, *p_blo, *p_ale, *p_was, *p_wad;
    cudaGetSymbolAddress(&p_deg, g_deg);
    cudaGetSymbolAddress(&p_yhi, g_yhi);
    cudaGetSymbolAddress(&p_ylo, g_ylo);
    cudaGetSymbolAddress(&p_hA, g_hA);
    cudaGetSymbolAddress(&p_hB, g_hB);
    cudaGetSymbolAddress(&p_bhi, g_bhi);
    cudaGetSymbolAddress(&p_blo, g_blo);
    cudaGetSymbolAddress(&p_ale, g_ale);
    cudaGetSymbolAddress(&p_was, g_Was);
    cudaGetSymbolAddress(&p_wad, g_Wad);
    __nv_bfloat16* yhi = (__nv_bfloat16*)p_yhi;
    __nv_bfloat16* ylo = (__nv_bfloat16*)p_ylo;
    float* hA = (float*)p_hA;
    float* hB = (float*)p_hB;
    __nv_bfloat16* bhi = (__nv_bfloat16*)p_bhi;
    __nv_bfloat16* blo = (__nv_bfloat16*)p_blo;
    float* ale = (float*)p_ale;
    float* wasp = (float*)p_was;
    float* wadp = (float*)p_wad;

    const int SMEM_BYTES = 61440;
    cudaFuncSetAttribute((const void*)k_hgemm<512, 128>,
                         cudaFuncAttributeMaxDynamicSharedMemorySize, SMEM_BYTES);
    cudaFuncSetAttribute((const void*)k_hgemm<512, 256>,
                         cudaFuncAttributeMaxDynamicSharedMemorySize, SMEM_BYTES);
    cudaFuncSetAttribute((const void*)k_hgemm<1024, 128>,
                         cudaFuncAttributeMaxDynamicSharedMemorySize, SMEM_BYTES);

    cudaMemsetAsync(p_deg, 0, NN * sizeof(int));

    k_deg<<<(EE + 255) / 256, 256>>>(dst);
    k_scan<<<1, 1024>>>();
    k_big<<<1249, 256>>>(dst,
                         W[0], We[0], As[0], Ad[0], Ae[0],
                         W[1], We[1], As[1], Ad[1], Ae[1],
                         W[2], We[2], As[2], Ad[2], Ae[2],
                         bhi, blo);

    const int Kdim[3] = {128, 128, 256};
    const size_t boff[3] = {0, 65536, 196608};
    const float* lin[3]  = {x, hA, hB};
    float*       lout[3] = {hA, hB, hA};
    const int MB = (NN + 63) / 64;   // 157

    // k_al(L0) BEFORE k_ale_all -> whichever slot rule ncu uses, the captured
    // kernel lands on k_al / k_ale_all / k_fsa (new evidence either way).
    k_al<<<(NN + 7) / 8, 256>>>(lin[0], wasp + 0 * 1024, wadp + 0 * 1024, Kdim[0]);
    k_ale_all<<<(EE / 2 + 127) / 128, 128>>>(eattr);

    for (int l = 0; l < 3; l++) {
        int Kd = Kdim[l];
        if (l > 0)
            k_al<<<(NN + 7) / 8, 256>>>(lin[l], wasp + l * 1024, wadp + l * 1024, Kd);
        if (Kd == 128)
            k_fsa<128><<<NN, 128>>>(src, lin[l], ale + (size_t)l * EE * HH, yhi, ylo);
        else
            k_fsa<256><<<NN, 128>>>(src, lin[l], ale + (size_t)l * EE * HH, yhi, ylo);
        if (l == 0)
            k_hgemm<512, 128><<<dim3(MB, 1), 256, SMEM_BYTES>>>(
                yhi, ylo, bhi + boff[0], blo + boff[0], Bb[0], lout[0]);
        else if (l == 1)
            k_hgemm<512, 256><<<dim3(MB, 2), 256, SMEM_BYTES>>>(
                yhi, ylo, bhi + boff[1], blo + boff[1], Bb[1], lout[1]);
        else
            k_hgemm<1024, 128><<<dim3(MB, 1), 256, SMEM_BYTES>>>(
                yhi, ylo, bhi + boff[2], blo + boff[2], Bb[2], lout[2]);
    }

    k_pool2<<<GG, 128>>>(batch, hA, out);
}